// round 7
// baseline (speedup 1.0000x reference)
#include <cuda_runtime.h>
#include <cstdint>
#include <math_constants.h>

// ---------------- problem constants ----------------
#define NNODES 50000
#define NEDGES 600000
#define C_IN   128
#define C_HID  256
#define C_OUT  47

// ---------------- static scratch (no allocation allowed) ----------------
__device__ __align__(128) float    g_h1  [(size_t)NNODES * C_HID];
__device__ __align__(128) float    g_h2  [(size_t)NNODES * C_HID];
__device__ __align__(128) float    g_zr  [(size_t)NNODES * 128];
__device__ __align__(128) float    g_agg3[(size_t)NNODES * 48];
__device__ __align__(128) float    g_inv [NNODES];
__device__ __align__(128) uint32_t g_aggH[(size_t)NNODES * 128];
__device__ __align__(128) uint32_t g_aggL[(size_t)NNODES * 128];
__device__ __align__(128) uint32_t g_xH  [(size_t)NNODES * 64];
__device__ __align__(128) uint32_t g_xL  [(size_t)NNODES * 64];
__device__ __align__(128) uint32_t g_h1H [(size_t)NNODES * 128];
__device__ __align__(128) uint32_t g_h1L [(size_t)NNODES * 128];
__device__ __align__(128) uint32_t g_h2H [(size_t)NNODES * 128];
__device__ __align__(128) uint32_t g_h2L [(size_t)NNODES * 128];
__device__ __align__(128) uint32_t g_W1H [256 * 128];
__device__ __align__(128) uint32_t g_W1L [256 * 128];
__device__ __align__(128) uint32_t g_W2H [256 * 256];
__device__ __align__(128) uint32_t g_W2L [256 * 256];
__device__ __align__(128) uint32_t g_W3H [96 * 128];
__device__ __align__(128) uint32_t g_W3L [96 * 128];
__device__ __align__(128) int      g_cnt [NNODES];
__device__ __align__(128) int      g_rowptr[NNODES + 1];
__device__ __align__(128) int      g_cursor[NNODES];
__device__ __align__(128) int      g_csr [NEDGES];
__device__ __align__(128) int      g_bsum[512];
__device__ int g_is64;

// ---------------- bf16 split helpers ----------------
__device__ __forceinline__ uint32_t pack_bf16(float e0, float e1) {
    uint32_t r;
    asm("cvt.rn.bf16x2.f32 %0, %1, %2;" : "=r"(r) : "f"(e1), "f"(e0));  // e0 -> low half
    return r;
}
__device__ __forceinline__ void split2(float a, float b, uint32_t& hi, uint32_t& lo) {
    hi = pack_bf16(a, b);
    float ha = __uint_as_float(hi << 16);
    float hb = __uint_as_float(hi & 0xffff0000u);
    lo = pack_bf16(a - ha, b - hb);
}

// ---------------- small helpers ----------------
__device__ __forceinline__ long long get_idx(const void* ei, long long i, int is64) {
    if (is64) return ((const long long*)ei)[i];
    return (long long)((const int*)ei)[i];
}

__global__ void detect_kernel(const int* ei32) {
    int bad = 0;
    for (int i = 2 * threadIdx.x + 1; i < 4096; i += 512) bad |= ei32[i];
    int any = __syncthreads_or(bad);
    if (threadIdx.x == 0) g_is64 = (any == 0) ? 1 : 0;
}

__global__ void zero_int_kernel(int* p, int n) {
    int i = blockIdx.x * blockDim.x + threadIdx.x;
    if (i < n) p[i] = 0;
}

__global__ void hist_kernel(const void* __restrict__ ei, int E, int* __restrict__ cnt) {
    int e = blockIdx.x * blockDim.x + threadIdx.x;
    if (e >= E) return;
    int is64 = g_is64;
    long long d = get_idx(ei, (long long)E + e, is64);
    atomicAdd(&cnt[d], 1);
}

__global__ void blocksum_kernel(const int* __restrict__ cnt, int* __restrict__ bsum, int M) {
    __shared__ int s[8];
    int i = blockIdx.x * 256 + threadIdx.x;
    int v = (i < M) ? cnt[i] : 0;
#pragma unroll
    for (int o = 16; o > 0; o >>= 1) v += __shfl_xor_sync(0xffffffffu, v, o);
    if ((threadIdx.x & 31) == 0) s[threadIdx.x >> 5] = v;
    __syncthreads();
    if (threadIdx.x == 0) {
        int t = 0;
#pragma unroll
        for (int w = 0; w < 8; w++) t += s[w];
        bsum[blockIdx.x] = t;
    }
}

__global__ void scanb_kernel(int* bsum, int nb) {
    __shared__ int s[512];
    int t = threadIdx.x;
    int v = (t < nb) ? bsum[t] : 0;
    s[t] = v;
    __syncthreads();
    for (int off = 1; off < 512; off <<= 1) {
        int u = (t >= off) ? s[t - off] : 0;
        __syncthreads();
        s[t] += u;
        __syncthreads();
    }
    if (t < nb) bsum[t] = s[t] - v;
}

__global__ void scan_final_kernel(const int* __restrict__ cnt, const int* __restrict__ bsum,
                                  int* __restrict__ rowptr, int* __restrict__ cursor,
                                  float* __restrict__ inv, int M) {
    __shared__ int s[256];
    int t = threadIdx.x;
    int i = blockIdx.x * 256 + t;
    int c = (i < M) ? cnt[i] : 0;
    s[t] = c;
    __syncthreads();
    for (int off = 1; off < 256; off <<= 1) {
        int u = (t >= off) ? s[t - off] : 0;
        __syncthreads();
        s[t] += u;
        __syncthreads();
    }
    if (i < M) {
        int rp = bsum[blockIdx.x] + s[t] - c;
        rowptr[i] = rp;
        cursor[i] = rp;
        inv[i] = 1.0f / fmaxf((float)c, 1.0f);
        if (i == M - 1) rowptr[M] = rp + c;
    }
}

__global__ void fill_kernel(const void* __restrict__ ei, int E,
                            int* __restrict__ cursor, int* __restrict__ csr) {
    int e = blockIdx.x * blockDim.x + threadIdx.x;
    if (e >= E) return;
    int is64 = g_is64;
    long long s = get_idx(ei, e, is64);
    long long d = get_idx(ei, (long long)E + e, is64);
    int slot = atomicAdd(&cursor[d], 1);
    csr[slot] = (int)s;
}

// ---------------- weight / input packing ----------------
__global__ void packw_kernel(const float* __restrict__ s1, int k1,
                             const float* __restrict__ s2, int k2,
                             uint32_t* __restrict__ H, uint32_t* __restrict__ L, int N) {
    int ktot = k1 + k2;
    int nu = ktot >> 1;
    int i = blockIdx.x * blockDim.x + threadIdx.x;
    if (i >= N * nu) return;
    int row = i / nu, j = i - row * nu;
    int f0 = 2 * j;
    float a, b;
    if (f0 < k1) { a = s1[(size_t)row * k1 + f0]; b = s1[(size_t)row * k1 + f0 + 1]; }
    else         { a = s2[(size_t)row * k2 + f0 - k1]; b = s2[(size_t)row * k2 + f0 - k1 + 1]; }
    uint32_t hi, lo;
    split2(a, b, hi, lo);
    H[i] = hi; L[i] = lo;
}

__global__ void packw3_kernel(const float* __restrict__ Wl3, const float* __restrict__ Wr3,
                              uint32_t* __restrict__ H, uint32_t* __restrict__ L) {
    int i = blockIdx.x * blockDim.x + threadIdx.x;
    if (i >= 96 * 128) return;
    int row = i >> 7, j = i & 127;
    float a = 0.f, b = 0.f;
    if (row < 47)      { a = Wl3[row * 256 + 2 * j]; b = Wl3[row * 256 + 2 * j + 1]; }
    else if (row < 94) { a = Wr3[(row - 47) * 256 + 2 * j]; b = Wr3[(row - 47) * 256 + 2 * j + 1]; }
    uint32_t hi, lo;
    split2(a, b, hi, lo);
    H[i] = hi; L[i] = lo;
}

// ---------------- gather-reduce: one warp per node ----------------
template <int NACC, int PACKED>
__global__ void gather_kernel(const float4* __restrict__ src, int src_ld4,
                              uint32_t* __restrict__ dH, uint32_t* __restrict__ dL,
                              float4* __restrict__ dF, int dst_ld, int nC4,
                              const int* __restrict__ rowptr, const int* __restrict__ csr,
                              const float* __restrict__ inv, int M) {
    int node = blockIdx.x * (blockDim.x >> 5) + (threadIdx.x >> 5);
    if (node >= M) return;
    int lane = threadIdx.x & 31;
    int beg = rowptr[node], end = rowptr[node + 1];
    float s = inv[node];
    float4 acc[NACC];
    bool act[NACC];
#pragma unroll
    for (int i = 0; i < NACC; i++) {
        acc[i] = make_float4(0.f, 0.f, 0.f, 0.f);
        act[i] = (lane + 32 * i) < nC4;
    }
    int e = beg;
    for (; e + 1 < end; e += 2) {
        const float4* r0 = src + (size_t)csr[e] * src_ld4;
        const float4* r1 = src + (size_t)csr[e + 1] * src_ld4;
#pragma unroll
        for (int i = 0; i < NACC; i++) {
            if (act[i]) {
                float4 v0 = r0[lane + 32 * i];
                float4 v1 = r1[lane + 32 * i];
                acc[i].x += v0.x; acc[i].y += v0.y; acc[i].z += v0.z; acc[i].w += v0.w;
                acc[i].x += v1.x; acc[i].y += v1.y; acc[i].z += v1.z; acc[i].w += v1.w;
            }
        }
    }
    if (e < end) {
        const float4* r0 = src + (size_t)csr[e] * src_ld4;
#pragma unroll
        for (int i = 0; i < NACC; i++) {
            if (act[i]) {
                float4 v0 = r0[lane + 32 * i];
                acc[i].x += v0.x; acc[i].y += v0.y; acc[i].z += v0.z; acc[i].w += v0.w;
            }
        }
    }
#pragma unroll
    for (int i = 0; i < NACC; i++) {
        if (!act[i]) continue;
        float4 v = acc[i];
        v.x *= s; v.y *= s; v.z *= s; v.w *= s;
        int col4 = lane + 32 * i;
        if (PACKED) {
            uint32_t h0, l0, h1, l1;
            split2(v.x, v.y, h0, l0);
            split2(v.z, v.w, h1, l1);
            uint2 hh = make_uint2(h0, h1);
            uint2 ll = make_uint2(l0, l1);
            *(uint2*)(dH + (size_t)node * dst_ld + col4 * 2) = hh;
            *(uint2*)(dL + (size_t)node * dst_ld + col4 * 2) = ll;
        } else {
            dF[(size_t)node * dst_ld + col4] = v;
        }
    }
}

// ---------------- bf16x3 warp-MMA GEMM (pre-packed operands, cp.async double-buffer) ----------------
// BROW=12 u32 (48B) -> 16B-aligned cp.async rows AND conflict-free fragment reads.
#define BROW 12

__device__ __forceinline__ uint32_t smem_u32(const void* p) {
    uint32_t a;
    asm("{ .reg .u64 t; cvta.to.shared.u64 t, %1; cvt.u32.u64 %0, t; }" : "=r"(a) : "l"(p));
    return a;
}
__device__ __forceinline__ void cpa16(uint32_t dst, const void* src, int sz) {
    asm volatile("cp.async.cg.shared.global [%0], [%1], 16, %2;"
                 :: "r"(dst), "l"(src), "r"(sz) : "memory");
}
__device__ __forceinline__ void mma_bf16(float* c, uint32_t a0, uint32_t a1, uint32_t a2, uint32_t a3,
                                         uint32_t b0, uint32_t b1) {
    asm volatile(
        "mma.sync.aligned.m16n8k16.row.col.f32.bf16.bf16.f32 "
        "{%0,%1,%2,%3}, {%4,%5,%6,%7}, {%8,%9}, {%0,%1,%2,%3};"
        : "+f"(c[0]), "+f"(c[1]), "+f"(c[2]), "+f"(c[3])
        : "r"(a0), "r"(a1), "r"(a2), "r"(a3), "r"(b0), "r"(b1));
}

__global__ void __launch_bounds__(256, 2)
gemm_bf16(const uint32_t* __restrict__ A1H, const uint32_t* __restrict__ A1L, int K1,
          const uint32_t* __restrict__ A2H, const uint32_t* __restrict__ A2L, int K2,
          const uint32_t* __restrict__ BH, const uint32_t* __restrict__ BL,
          float* __restrict__ C, int ldc,
          uint32_t* __restrict__ CH, uint32_t* __restrict__ CL, int ldch,
          int M, int N, int do_relu) {
    __shared__ uint32_t sbuf[2][4][128 * BROW];

    const int tid = threadIdx.x;
    const int wid = tid >> 5;
    const int lid = tid & 31;
    const int gID = lid >> 2;
    const int tig = lid & 3;
    const int warp_m = wid & 3;
    const int warp_n = wid >> 2;
    const int m_base = blockIdx.y * 128;
    const int n_base = blockIdx.x * 128;
    const int K = K1 + K2;
    const int nchunks = K >> 4;
    const int ldb = K >> 1;
    const int k1u = K1 >> 1;
    const uint32_t sb = smem_u32(&sbuf[0][0][0]);

    const int crow = tid >> 1;
    const int chalf = tid & 1;
    const int mg = m_base + crow;
    const int ng = n_base + crow;
    const int szA = (mg < M) ? 16 : 0;
    const int szB = (ng < N) ? 16 : 0;
    const uint32_t doff = (uint32_t)(crow * BROW + chalf * 4) * 4;   // 48B rows -> 16B aligned

    float acc[2][8][4];
#pragma unroll
    for (int mi = 0; mi < 2; mi++)
#pragma unroll
        for (int ni = 0; ni < 8; ni++)
#pragma unroll
            for (int j = 0; j < 4; j++) acc[mi][ni][j] = 0.f;

    auto copy_chunk = [&](int kc, int s) {
        int ku = (kc << 3) + chalf * 4;
        const uint32_t *ah, *al;
        if (ku < k1u) {
            ah = A1H + (size_t)mg * k1u + ku;
            al = A1L + (size_t)mg * k1u + ku;
        } else {
            int k2u = K2 >> 1;
            ah = A2H + (size_t)mg * k2u + (ku - k1u);
            al = A2L + (size_t)mg * k2u + (ku - k1u);
        }
        uint32_t base = sb + (uint32_t)(s * 4) * (128 * BROW * 4);
        cpa16(base + doff,                        ah, szA);
        cpa16(base + 128 * BROW * 4 + doff,       al, szA);
        const uint32_t* bh = BH + (size_t)ng * ldb + ku;
        const uint32_t* bl = BL + (size_t)ng * ldb + ku;
        cpa16(base + 2 * 128 * BROW * 4 + doff,   bh, szB);
        cpa16(base + 3 * 128 * BROW * 4 + doff,   bl, szB);
    };

    copy_chunk(0, 0);
    asm volatile("cp.async.commit_group;" ::: "memory");

    for (int kc = 0; kc < nchunks; kc++) {
        int s = kc & 1;
        if (kc + 1 < nchunks) {
            copy_chunk(kc + 1, (kc + 1) & 1);
            asm volatile("cp.async.commit_group;" ::: "memory");
            asm volatile("cp.async.wait_group 1;" ::: "memory");
        } else {
            asm volatile("cp.async.wait_group 0;" ::: "memory");
        }
        __syncthreads();

        const uint32_t* Ah = sbuf[s][0];
        const uint32_t* Al = sbuf[s][1];
        const uint32_t* Bh = sbuf[s][2];
        const uint32_t* Bl = sbuf[s][3];

        uint32_t ah[2][4], al[2][4];
#pragma unroll
        for (int mi = 0; mi < 2; mi++) {
            int rm = warp_m * 32 + mi * 16;
            int r0 = (rm + gID) * BROW + tig;
            int r1 = (rm + gID + 8) * BROW + tig;
            ah[mi][0] = Ah[r0];     ah[mi][1] = Ah[r1];
            ah[mi][2] = Ah[r0 + 4]; ah[mi][3] = Ah[r1 + 4];
            al[mi][0] = Al[r0];     al[mi][1] = Al[r1];
            al[mi][2] = Al[r0 + 4]; al[mi][3] = Al[r1 + 4];
        }
#pragma unroll
        for (int ni = 0; ni < 8; ni++) {
            int nn = warp_n * 64 + ni * 8 + gID;
            int o = nn * BROW + tig;
            uint32_t bh0 = Bh[o], bh1 = Bh[o + 4];
            uint32_t bl0 = Bl[o], bl1 = Bl[o + 4];
#pragma unroll
            for (int mi = 0; mi < 2; mi++) {
                mma_bf16(acc[mi][ni], ah[mi][0], ah[mi][1], ah[mi][2], ah[mi][3], bh0, bh1);
                mma_bf16(acc[mi][ni], ah[mi][0], ah[mi][1], ah[mi][2], ah[mi][3], bl0, bl1);
                mma_bf16(acc[mi][ni], al[mi][0], al[mi][1], al[mi][2], al[mi][3], bh0, bh1);
            }
        }
        __syncthreads();
    }

    // ---- epilogue: fp32 C + optional packed bf16 hi/lo ----
#pragma unroll
    for (int mi = 0; mi < 2; mi++) {
#pragma unroll
        for (int ni = 0; ni < 8; ni++) {
            int col = n_base + warp_n * 64 + ni * 8 + 2 * tig;
            if (col >= N) continue;
            int r0 = m_base + warp_m * 32 + mi * 16 + gID;
            int r1 = r0 + 8;
            float2 v0 = make_float2(acc[mi][ni][0], acc[mi][ni][1]);
            float2 v1 = make_float2(acc[mi][ni][2], acc[mi][ni][3]);
            if (do_relu) {
                v0.x = fmaxf(v0.x, 0.f); v0.y = fmaxf(v0.y, 0.f);
                v1.x = fmaxf(v1.x, 0.f); v1.y = fmaxf(v1.y, 0.f);
            }
            if (r0 < M) {
                *(float2*)(C + (size_t)r0 * ldc + col) = v0;
                if (CH) {
                    uint32_t hi, lo;
                    split2(v0.x, v0.y, hi, lo);
                    CH[(size_t)r0 * ldch + (col >> 1)] = hi;
                    CL[(size_t)r0 * ldch + (col >> 1)] = lo;
                }
            }
            if (r1 < M) {
                *(float2*)(C + (size_t)r1 * ldc + col) = v1;
                if (CH) {
                    uint32_t hi, lo;
                    split2(v1.x, v1.y, hi, lo);
                    CH[(size_t)r1 * ldch + (col >> 1)] = hi;
                    CL[(size_t)r1 * ldch + (col >> 1)] = lo;
                }
            }
        }
    }
}

// ---------------- final: out = log_softmax(agg3 + r) (inv already applied) ----------------
__global__ void final_kernel(const float* __restrict__ agg3, const float* __restrict__ zr,
                             float* __restrict__ out, int M) {
    int m = blockIdx.x * blockDim.y + threadIdx.y;
    if (m >= M) return;
    int lane = threadIdx.x;
    float v1 = -CUDART_INF_F, v2 = -CUDART_INF_F;
    if (lane < 47)
        v1 = agg3[(size_t)m * 48 + lane] + zr[(size_t)m * 128 + 47 + lane];
    int c2 = lane + 32;
    if (c2 < 47)
        v2 = agg3[(size_t)m * 48 + c2] + zr[(size_t)m * 128 + 47 + c2];
    float mx = fmaxf(v1, v2);
#pragma unroll
    for (int o = 16; o > 0; o >>= 1) mx = fmaxf(mx, __shfl_xor_sync(0xffffffffu, mx, o));
    float s = 0.f;
    if (lane < 47) s += expf(v1 - mx);
    if (c2 < 47)   s += expf(v2 - mx);
#pragma unroll
    for (int o = 16; o > 0; o >>= 1) s += __shfl_xor_sync(0xffffffffu, s, o);
    float lse = logf(s);
    if (lane < 47) out[(size_t)m * 47 + lane] = v1 - mx - lse;
    if (c2 < 47)   out[(size_t)m * 47 + c2]   = v2 - mx - lse;
}

// ---------------- launch ----------------
extern "C" void kernel_launch(void* const* d_in, const int* in_sizes, int n_in,
                              void* d_out, int out_size) {
    const float* x   = (const float*)d_in[0];
    const float* Wl1 = (const float*)d_in[1];
    const float* Wr1 = (const float*)d_in[2];
    const float* Wl2 = (const float*)d_in[3];
    const float* Wr2 = (const float*)d_in[4];
    const float* Wl3 = (const float*)d_in[5];
    const float* Wr3 = (const float*)d_in[6];
    const void*  ei  = d_in[7];
    const int E = in_sizes[7] / 2;
    const int M = in_sizes[0] / C_IN;
    float* out = (float*)d_out;

    float *h1, *h2, *zr, *agg3, *inv;
    uint32_t *aggH, *aggL, *xH, *xL, *h1H, *h1L, *h2H, *h2L;
    uint32_t *W1H, *W1L, *W2H, *W2L, *W3H, *W3L;
    int *cnt, *rowptr, *cursor, *csr, *bsum;
    cudaGetSymbolAddress((void**)&h1,     g_h1);
    cudaGetSymbolAddress((void**)&h2,     g_h2);
    cudaGetSymbolAddress((void**)&zr,     g_zr);
    cudaGetSymbolAddress((void**)&agg3,   g_agg3);
    cudaGetSymbolAddress((void**)&inv,    g_inv);
    cudaGetSymbolAddress((void**)&aggH,   g_aggH);
    cudaGetSymbolAddress((void**)&aggL,   g_aggL);
    cudaGetSymbolAddress((void**)&xH,     g_xH);
    cudaGetSymbolAddress((void**)&xL,     g_xL);
    cudaGetSymbolAddress((void**)&h1H,    g_h1H);
    cudaGetSymbolAddress((void**)&h1L,    g_h1L);
    cudaGetSymbolAddress((void**)&h2H,    g_h2H);
    cudaGetSymbolAddress((void**)&h2L,    g_h2L);
    cudaGetSymbolAddress((void**)&W1H,    g_W1H);
    cudaGetSymbolAddress((void**)&W1L,    g_W1L);
    cudaGetSymbolAddress((void**)&W2H,    g_W2H);
    cudaGetSymbolAddress((void**)&W2L,    g_W2L);
    cudaGetSymbolAddress((void**)&W3H,    g_W3H);
    cudaGetSymbolAddress((void**)&W3L,    g_W3L);
    cudaGetSymbolAddress((void**)&cnt,    g_cnt);
    cudaGetSymbolAddress((void**)&rowptr, g_rowptr);
    cudaGetSymbolAddress((void**)&cursor, g_cursor);
    cudaGetSymbolAddress((void**)&csr,    g_csr);
    cudaGetSymbolAddress((void**)&bsum,   g_bsum);

    detect_kernel<<<1, 256>>>((const int*)ei);

    // ---- CSR build ----
    const int nb = (M + 255) / 256;
    zero_int_kernel<<<nb, 256>>>(cnt, M);
    hist_kernel<<<(E + 255) / 256, 256>>>(ei, E, cnt);
    blocksum_kernel<<<nb, 256>>>(cnt, bsum, M);
    scanb_kernel<<<1, 512>>>(bsum, nb);
    scan_final_kernel<<<nb, 256>>>(cnt, bsum, rowptr, cursor, inv, M);
    fill_kernel<<<(E + 255) / 256, 256>>>(ei, E, cursor, csr);

    // ---- pack weights + x ----
    packw_kernel<<<(256 * 128 + 255) / 256, 256>>>(Wl1, 128, Wr1, 128, W1H, W1L, 256);
    packw_kernel<<<(256 * 256 + 255) / 256, 256>>>(Wl2, 256, Wr2, 256, W2H, W2L, 256);
    packw3_kernel<<<(96 * 128 + 255) / 256, 256>>>(Wl3, Wr3, W3H, W3L);
    packw_kernel<<<((M * 64) + 255) / 256, 256>>>(x, 128, (const float*)nullptr, 0, xH, xL, M);

    const int gat_blocks = (M + 7) / 8;
    const int grid_m = (M + 127) / 128;

    // ---- layer 1 ----
    gather_kernel<1, 1><<<gat_blocks, 256>>>((const float4*)x, 32,
                                             aggH, aggL, nullptr, 64, 32,
                                             rowptr, csr, inv, M);
    gemm_bf16<<<dim3(2, grid_m), 256>>>(aggH, aggL, 128, xH, xL, 128,
                                        W1H, W1L, h1, 256, h1H, h1L, 128,
                                        M, 256, 1);

    // ---- layer 2 ----
    gather_kernel<2, 1><<<gat_blocks, 256>>>((const float4*)h1, 64,
                                             aggH, aggL, nullptr, 128, 64,
                                             rowptr, csr, inv, M);
    gemm_bf16<<<dim3(2, grid_m), 256>>>(aggH, aggL, 256, h1H, h1L, 256,
                                        W2H, W2L, h2, 256, h2H, h2L, 128,
                                        M, 256, 1);

    // ---- layer 3: transform-first ----
    gemm_bf16<<<dim3(1, grid_m), 256>>>(h2H, h2L, 256, (const uint32_t*)nullptr, (const uint32_t*)nullptr, 0,
                                        W3H, W3L, zr, 128, nullptr, nullptr, 0,
                                        M, 96, 0);
    gather_kernel<1, 0><<<gat_blocks, 256>>>((const float4*)zr, 32,
                                             nullptr, nullptr, (float4*)agg3, 12, 12,
                                             rowptr, csr, inv, M);

    dim3 blk(32, 8);
    final_kernel<<<(M + 7) / 8, blk>>>(agg3, zr, out, M);
}

// round 10
// speedup vs baseline: 1.2068x; 1.2068x over previous
#include <cuda_runtime.h>
#include <cuda_fp16.h>
#include <cstdint>
#include <math_constants.h>

#define NNODES 50000
#define NEDGES 600000
#define C_IN   128
#define C_HID  256
#define C_OUT  47

__device__ __align__(128) float    g_h1  [(size_t)NNODES * C_HID];
__device__ __align__(128) float    g_zr  [(size_t)NNODES * 128];
__device__ __align__(128) float    g_agg3[(size_t)NNODES * 48];
__device__ __align__(128) float    g_inv [NNODES];
__device__ __align__(128) uint32_t g_aggH[(size_t)NNODES * 128];
__device__ __align__(128) uint32_t g_aggL[(size_t)NNODES * 128];
__device__ __align__(128) uint32_t g_xH  [(size_t)NNODES * 64];
__device__ __align__(128) uint32_t g_xL  [(size_t)NNODES * 64];
__device__ __align__(128) uint32_t g_h1H [(size_t)NNODES * 128];
__device__ __align__(128) uint32_t g_h1L [(size_t)NNODES * 128];
__device__ __align__(128) uint32_t g_h2H [(size_t)NNODES * 128];
__device__ __align__(128) uint32_t g_h2L [(size_t)NNODES * 128];
__device__ __align__(128) uint32_t g_W1H [256 * 128];
__device__ __align__(128) uint32_t g_W2H [256 * 256];
__device__ __align__(128) uint32_t g_W3H [96 * 128];
__device__ __align__(128) int      g_cnt [NNODES];
__device__ __align__(128) int      g_rowptr[NNODES + 1];
__device__ __align__(128) int      g_cursor[NNODES];
__device__ __align__(128) int      g_csr [NEDGES];
__device__ __align__(128) int      g_bsum[512];
__device__ int g_is64;

__device__ __forceinline__ void split2f(float a, float b, uint32_t& hi, uint32_t& lo) {
    __half2 h = __floats2half2_rn(a, b);
    float2 hf = __half22float2(h);
    __half2 l = __floats2half2_rn(a - hf.x, b - hf.y);
    hi = *reinterpret_cast<uint32_t*>(&h);
    lo = *reinterpret_cast<uint32_t*>(&l);
}
__device__ __forceinline__ uint32_t packh(float a, float b) {
    __half2 h = __floats2half2_rn(a, b);
    return *reinterpret_cast<uint32_t*>(&h);
}

__device__ __forceinline__ long long get_idx(const void* ei, long long i, int is64) {
    if (is64) return ((const long long*)ei)[i];
    return (long long)((const int*)ei)[i];
}

__global__ void detect_kernel(const int* ei32) {
    int bad = 0;
    for (int i = 2 * threadIdx.x + 1; i < 4096; i += 512) bad |= ei32[i];
    int any = __syncthreads_or(bad);
    if (threadIdx.x == 0) g_is64 = (any == 0) ? 1 : 0;
}

__global__ void zero_int_kernel(int* p, int n) {
    int i = blockIdx.x * blockDim.x + threadIdx.x;
    if (i < n) p[i] = 0;
}

__global__ void hist_kernel(const void* __restrict__ ei, int E, int* __restrict__ cnt) {
    int e = blockIdx.x * blockDim.x + threadIdx.x;
    if (e >= E) return;
    int is64 = g_is64;
    long long d = get_idx(ei, (long long)E + e, is64);
    atomicAdd(&cnt[d], 1);
}

__global__ void blocksum_kernel(const int* __restrict__ cnt, int* __restrict__ bsum, int M) {
    __shared__ int s[8];
    int i = blockIdx.x * 256 + threadIdx.x;
    int v = (i < M) ? cnt[i] : 0;
#pragma unroll
    for (int o = 16; o > 0; o >>= 1) v += __shfl_xor_sync(0xffffffffu, v, o);
    if ((threadIdx.x & 31) == 0) s[threadIdx.x >> 5] = v;
    __syncthreads();
    if (threadIdx.x == 0) {
        int t = 0;
#pragma unroll
        for (int w = 0; w < 8; w++) t += s[w];
        bsum[blockIdx.x] = t;
    }
}

__global__ void scanb_kernel(int* bsum, int nb) {
    __shared__ int s[512];
    int t = threadIdx.x;
    int v = (t < nb) ? bsum[t] : 0;
    s[t] = v;
    __syncthreads();
    for (int off = 1; off < 512; off <<= 1) {
        int u = (t >= off) ? s[t - off] : 0;
        __syncthreads();
        s[t] += u;
        __syncthreads();
    }
    if (t < nb) bsum[t] = s[t] - v;
}

__global__ void scan_final_kernel(const int* __restrict__ cnt, const int* __restrict__ bsum,
                                  int* __restrict__ rowptr, int* __restrict__ cursor,
                                  float* __restrict__ inv, int M) {
    __shared__ int s[256];
    int t = threadIdx.x;
    int i = blockIdx.x * 256 + t;
    int c = (i < M) ? cnt[i] : 0;
    s[t] = c;
    __syncthreads();
    for (int off = 1; off < 256; off <<= 1) {
        int u = (t >= off) ? s[t - off] : 0;
        __syncthreads();
        s[t] += u;
        __syncthreads();
    }
    if (i < M) {
        int rp = bsum[blockIdx.x] + s[t] - c;
        rowptr[i] = rp;
        cursor[i] = rp;
        inv[i] = 1.0f / fmaxf((float)c, 1.0f);
        if (i == M - 1) rowptr[M] = rp + c;
    }
}

__global__ void fill_kernel(const void* __restrict__ ei, int E,
                            int* __restrict__ cursor, int* __restrict__ csr) {
    int e = blockIdx.x * blockDim.x + threadIdx.x;
    if (e >= E) return;
    int is64 = g_is64;
    long long s = get_idx(ei, e, is64);
    long long d = get_idx(ei, (long long)E + e, is64);
    int slot = atomicAdd(&cursor[d], 1);
    csr[slot] = (int)s;
}

__global__ void packw_kernel(const float* __restrict__ s1, int k1,
                             const float* __restrict__ s2, int k2,
                             uint32_t* __restrict__ H, uint32_t* __restrict__ L, int N) {
    int ktot = k1 + k2;
    int nu = ktot >> 1;
    int i = blockIdx.x * blockDim.x + threadIdx.x;
    if (i >= N * nu) return;
    int row = i / nu, j = i - row * nu;
    int f0 = 2 * j;
    float a, b;
    if (f0 < k1) { a = s1[(size_t)row * k1 + f0]; b = s1[(size_t)row * k1 + f0 + 1]; }
    else         { a = s2[(size_t)row * k2 + f0 - k1]; b = s2[(size_t)row * k2 + f0 - k1 + 1]; }
    if (L) {
        uint32_t hi, lo;
        split2f(a, b, hi, lo);
        H[i] = hi; L[i] = lo;
    } else {
        H[i] = packh(a, b);
    }
}

__global__ void packw3_kernel(const float* __restrict__ Wl3, const float* __restrict__ Wr3,
                              uint32_t* __restrict__ H) {
    int i = blockIdx.x * blockDim.x + threadIdx.x;
    if (i >= 96 * 128) return;
    int row = i >> 7, j = i & 127;
    float a = 0.f, b = 0.f;
    if (row < 47)      { a = Wl3[row * 256 + 2 * j]; b = Wl3[row * 256 + 2 * j + 1]; }
    else if (row < 94) { a = Wr3[(row - 47) * 256 + 2 * j]; b = Wr3[(row - 47) * 256 + 2 * j + 1]; }
    H[i] = packh(a, b);
}

template <int NACC, int PACKED>
__global__ void gather_kernel(const float4* __restrict__ src, int src_ld4,
                              uint32_t* __restrict__ dH, uint32_t* __restrict__ dL,
                              float4* __restrict__ dF, int dst_ld, int nC4,
                              const int* __restrict__ rowptr, const int* __restrict__ csr,
                              const float* __restrict__ inv, int M) {
    int node = blockIdx.x * (blockDim.x >> 5) + (threadIdx.x >> 5);
    if (node >= M) return;
    int lane = threadIdx.x & 31;
    int beg = rowptr[node], end = rowptr[node + 1];
    float s = inv[node];
    float4 acc[NACC];
    bool act[NACC];
#pragma unroll
    for (int i = 0; i < NACC; i++) {
        acc[i] = make_float4(0.f, 0.f, 0.f, 0.f);
        act[i] = (lane + 32 * i) < nC4;
    }
    int e = beg;
    for (; e + 1 < end; e += 2) {
        const float4* r0 = src + (size_t)csr[e] * src_ld4;
        const float4* r1 = src + (size_t)csr[e + 1] * src_ld4;
#pragma unroll
        for (int i = 0; i < NACC; i++) {
            if (act[i]) {
                float4 v0 = r0[lane + 32 * i];
                float4 v1 = r1[lane + 32 * i];
                acc[i].x += v0.x; acc[i].y += v0.y; acc[i].z += v0.z; acc[i].w += v0.w;
                acc[i].x += v1.x; acc[i].y += v1.y; acc[i].z += v1.z; acc[i].w += v1.w;
            }
        }
    }
    if (e < end) {
        const float4* r0 = src + (size_t)csr[e] * src_ld4;
#pragma unroll
        for (int i = 0; i < NACC; i++) {
            if (act[i]) {
                float4 v0 = r0[lane + 32 * i];
                acc[i].x += v0.x; acc[i].y += v0.y; acc[i].z += v0.z; acc[i].w += v0.w;
            }
        }
    }
#pragma unroll
    for (int i = 0; i < NACC; i++) {
        if (!act[i]) continue;
        float4 v = acc[i];
        v.x *= s; v.y *= s; v.z *= s; v.w *= s;
        int col4 = lane + 32 * i;
        if (PACKED) {
            uint32_t h0, l0, h1, l1;
            split2f(v.x, v.y, h0, l0);
            split2f(v.z, v.w, h1, l1);
            *(uint2*)(dH + (size_t)node * dst_ld + col4 * 2) = make_uint2(h0, h1);
            *(uint2*)(dL + (size_t)node * dst_ld + col4 * 2) = make_uint2(l0, l1);
        } else {
            dF[(size_t)node * dst_ld + col4] = v;
        }
    }
}

#define BROW 12

__device__ __forceinline__ uint32_t smem_u32(const void* p) {
    uint32_t a;
    asm("{ .reg .u64 t; cvta.to.shared.u64 t, %1; cvt.u32.u64 %0, t; }" : "=r"(a) : "l"(p));
    return a;
}
__device__ __forceinline__ void cpa16(uint32_t dst, const void* src, int sz) {
    asm volatile("cp.async.cg.shared.global [%0], [%1], 16, %2;"
                 :: "r"(dst), "l"(src), "r"(sz) : "memory");
}
__device__ __forceinline__ void mma_f16(float* c, uint32_t a0, uint32_t a1, uint32_t a2, uint32_t a3,
                                        uint32_t b0, uint32_t b1) {
    asm volatile(
        "mma.sync.aligned.m16n8k16.row.col.f32.f16.f16.f32 "
        "{%0,%1,%2,%3}, {%4,%5,%6,%7}, {%8,%9}, {%0,%1,%2,%3};"
        : "+f"(c[0]), "+f"(c[1]), "+f"(c[2]), "+f"(c[3])
        : "r"(a0), "r"(a1), "r"(a2), "r"(a3), "r"(b0), "r"(b1));
}

__global__ void __launch_bounds__(256, 2)
gemm_f16(const uint32_t* __restrict__ A1H, const uint32_t* __restrict__ A1L, int K1,
         const uint32_t* __restrict__ A2H, const uint32_t* __restrict__ A2L, int K2,
         const uint32_t* __restrict__ BH,
         float* __restrict__ C, int ldc,
         uint32_t* __restrict__ CH, uint32_t* __restrict__ CL, int ldch,
         int M, int N, int do_relu) {
    __shared__ uint32_t sbuf[2][3][128 * BROW];

    const int tid = threadIdx.x;
    const int wid = tid >> 5;
    const int lid = tid & 31;
    const int gID = lid >> 2;
    const int tig = lid & 3;
    const int warp_m = wid & 3;
    const int warp_n = wid >> 2;
    const int m_base = blockIdx.y * 128;
    const int n_base = blockIdx.x * 128;
    const int K = K1 + K2;
    const int nchunks = K >> 4;
    const int ldb = K >> 1;
    const int k1u = K1 >> 1;
    const uint32_t sb = smem_u32(&sbuf[0][0][0]);

    const int crow = tid >> 1;
    const int chalf = tid & 1;
    const int mg = m_base + crow;
    const int ng = n_base + crow;
    const int szA = (mg < M) ? 16 : 0;
    const int szB = (ng < N) ? 16 : 0;
    const uint32_t doff = (uint32_t)(crow * BROW + chalf * 4) * 4;

    float acc[2][8][4];
#pragma unroll
    for (int mi = 0; mi < 2; mi++)
#pragma unroll
        for (int ni = 0; ni < 8; ni++)
#pragma unroll
            for (int j = 0; j < 4; j++) acc[mi][ni][j] = 0.f;

    auto copy_chunk = [&](int kc, int s) {
        int ku = (kc << 3) + chalf * 4;
        const uint32_t *ah, *al;
        if (ku < k1u) {
            ah = A1H + (size_t)mg * k1u + ku;
            al = A1L + (size_t)mg * k1u + ku;
        } else {
            int k2u = K2 >> 1;
            ah = A2H + (size_t)mg * k2u + (ku - k1u);
            al = A2L + (size_t)mg * k2u + (ku - k1u);
        }
        uint32_t base = sb + (uint32_t)(s * 3) * (128 * BROW * 4);
        cpa16(base + doff,                      ah, szA);
        cpa16(base + 128 * BROW * 4 + doff,     al, szA);
        const uint32_t* bh = BH + (size_t)ng * ldb + ku;
        cpa16(base + 2 * 128 * BROW * 4 + doff, bh, szB);
    };

    copy_chunk(0, 0);
    asm volatile("cp.async.commit_group;" ::: "memory");

    for (int kc = 0; kc < nchunks; kc++) {
        int s = kc & 1;
        if (kc + 1 < nchunks) {
            copy_chunk(kc + 1, (kc + 1) & 1);
            asm volatile("cp.async.commit_group;" ::: "memory");
            asm volatile("cp.async.wait_group 1;" ::: "memory");
        } else {
            asm volatile("cp.async.wait_group 0;" ::: "memory");
        }
        __syncthreads();

        const uint32_t* Ah = sbuf[s][0];
        const uint32_t* Al = sbuf[s][1];
        const uint32_t* Bh = sbuf[s][2];

        uint32_t ah[2][4], al[2][4];
#pragma unroll
        for (int mi = 0; mi < 2; mi++) {
            int rm = warp_m * 32 + mi * 16;
            int r0 = (rm + gID) * BROW + tig;
            int r1 = (rm + gID + 8) * BROW + tig;
            ah[mi][0] = Ah[r0];     ah[mi][1] = Ah[r1];
            ah[mi][2] = Ah[r0 + 4]; ah[mi][3] = Ah[r1 + 4];
            al[mi][0] = Al[r0];     al[mi][1] = Al[r1];
            al[mi][2] = Al[r0 + 4]; al[mi][3] = Al[r1 + 4];
        }
#pragma unroll
        for (int ni = 0; ni < 8; ni++) {
            int nn = warp_n * 64 + ni * 8 + gID;
            int o = nn * BROW + tig;
            uint32_t bh0 = Bh[o], bh1 = Bh[o + 4];
#pragma unroll
            for (int mi = 0; mi < 2; mi++) {
                mma_f16(acc[mi][ni], ah[mi][0], ah[mi][1], ah[mi][2], ah[mi][3], bh0, bh1);
                mma_f16(acc[mi][ni], al[mi][0], al[mi][1], al[mi][2], al[mi][3], bh0, bh1);
            }
        }
        __syncthreads();
    }

#pragma unroll
    for (int mi = 0; mi < 2; mi++) {
#pragma unroll
        for (int ni = 0; ni < 8; ni++) {
            int col = n_base + warp_n * 64 + ni * 8 + 2 * tig;
            if (col >= N) continue;
            int r0 = m_base + warp_m * 32 + mi * 16 + gID;
            int r1 = r0 + 8;
            float2 v0 = make_float2(acc[mi][ni][0], acc[mi][ni][1]);
            float2 v1 = make_float2(acc[mi][ni][2], acc[mi][ni][3]);
            if (do_relu) {
                v0.x = fmaxf(v0.x, 0.f); v0.y = fmaxf(v0.y, 0.f);
                v1.x = fmaxf(v1.x, 0.f); v1.y = fmaxf(v1.y, 0.f);
            }
            if (r0 < M) {
                if (C) *(float2*)(C + (size_t)r0 * ldc + col) = v0;
                if (CH) {
                    uint32_t hi, lo;
                    split2f(v0.x, v0.y, hi, lo);
                    CH[(size_t)r0 * ldch + (col >> 1)] = hi;
                    CL[(size_t)r0 * ldch + (col >> 1)] = lo;
                }
            }
            if (r1 < M) {
                if (C) *(float2*)(C + (size_t)r1 * ldc + col) = v1;
                if (CH) {
                    uint32_t hi, lo;
                    split2f(v1.x, v1.y, hi, lo);
                    CH[(size_t)r1 * ldch + (col >> 1)] = hi;
                    CL[(size_t)r1 * ldch + (col >> 1)] = lo;
                }
            }
        }
    }
}

__global__ void final_kernel(const float* __restrict__ agg3, const float* __restrict__ zr,
                             float* __restrict__ out, int M) {
    int m = blockIdx.x * blockDim.y + threadIdx.y;
    if (m >= M) return;
    int lane = threadIdx.x;
    float v1 = -CUDART_INF_F, v2 = -CUDART_INF_F;
    if (lane < 47)
        v1 = agg3[(size_t)m * 48 + lane] + zr[(size_t)m * 128 + 47 + lane];
    int c2 = lane + 32;
    if (c2 < 47)
        v2 = agg3[(size_t)m * 48 + c2] + zr[(size_t)m * 128 + 47 + c2];
    float mx = fmaxf(v1, v2);
#pragma unroll
    for (int o = 16; o > 0; o >>= 1) mx = fmaxf(mx, __shfl_xor_sync(0xffffffffu, mx, o));
    float s = 0.f;
    if (lane < 47) s += expf(v1 - mx);
    if (c2 < 47)   s += expf(v2 - mx);
#pragma unroll
    for (int o = 16; o > 0; o >>= 1) s += __shfl_xor_sync(0xffffffffu, s, o);
    float lse = logf(s);
    if (lane < 47) out[(size_t)m * 47 + lane] = v1 - mx - lse;
    if (c2 < 47)   out[(size_t)m * 47 + c2]   = v2 - mx - lse;
}

extern "C" void kernel_launch(void* const* d_in, const int* in_sizes, int n_in,
                              void* d_out, int out_size) {
    const float* x   = (const float*)d_in[0];
    const float* Wl1 = (const float*)d_in[1];
    const float* Wr1 = (const float*)d_in[2];
    const float* Wl2 = (const float*)d_in[3];
    const float* Wr2 = (const float*)d_in[4];
    const float* Wl3 = (const float*)d_in[5];
    const float* Wr3 = (const float*)d_in[6];
    const void*  ei  = d_in[7];
    const int E = in_sizes[7] / 2;
    const int M = in_sizes[0] / C_IN;
    float* out = (float*)d_out;

    float *h1, *zr, *agg3, *inv;
    uint32_t *aggH, *aggL, *xH, *xL, *h1H, *h1L, *h2H, *h2L;
    uint32_t *W1H, *W2H, *W3H;
    int *cnt, *rowptr, *cursor, *csr, *bsum;
    cudaGetSymbolAddress((void**)&h1,     g_h1);
    cudaGetSymbolAddress((void**)&zr,     g_zr);
    cudaGetSymbolAddress((void**)&agg3,   g_agg3);
    cudaGetSymbolAddress((void**)&inv,    g_inv);
    cudaGetSymbolAddress((void**)&aggH,   g_aggH);
    cudaGetSymbolAddress((void**)&aggL,   g_aggL);
    cudaGetSymbolAddress((void**)&xH,     g_xH);
    cudaGetSymbolAddress((void**)&xL,     g_xL);
    cudaGetSymbolAddress((void**)&h1H,    g_h1H);
    cudaGetSymbolAddress((void**)&h1L,    g_h1L);
    cudaGetSymbolAddress((void**)&h2H,    g_h2H);
    cudaGetSymbolAddress((void**)&h2L,    g_h2L);
    cudaGetSymbolAddress((void**)&W1H,    g_W1H);
    cudaGetSymbolAddress((void**)&W2H,    g_W2H);
    cudaGetSymbolAddress((void**)&W3H,    g_W3H);
    cudaGetSymbolAddress((void**)&cnt,    g_cnt);
    cudaGetSymbolAddress((void**)&rowptr, g_rowptr);
    cudaGetSymbolAddress((void**)&cursor, g_cursor);
    cudaGetSymbolAddress((void**)&csr,    g_csr);
    cudaGetSymbolAddress((void**)&bsum,   g_bsum);

    detect_kernel<<<1, 256>>>((const int*)ei);

    const int nb = (M + 255) / 256;
    zero_int_kernel<<<nb, 256>>>(cnt, M);
    hist_kernel<<<(E + 255) / 256, 256>>>(ei, E, cnt);
    blocksum_kernel<<<nb, 256>>>(cnt, bsum, M);
    scanb_kernel<<<1, 512>>>(bsum, nb);
    scan_final_kernel<<<nb, 256>>>(cnt, bsum, rowptr, cursor, inv, M);
    fill_kernel<<<(E + 255) / 256, 256>>>(ei, E, cursor, csr);

    packw_kernel<<<(256 * 128 + 255) / 256, 256>>>(Wl1, 128, Wr1, 128, W1H, nullptr, 256);
    packw_kernel<<<(256 * 256 + 255) / 256, 256>>>(Wl2, 256, Wr2, 256, W2H, nullptr, 256);
    packw3_kernel<<<(96 * 128 + 255) / 256, 256>>>(Wl3, Wr3, W3H);
    packw_kernel<<<((M * 64) + 255) / 256, 256>>>(x, 128, (const float*)nullptr, 0, xH, xL, M);

    const int gat_blocks = (M + 7) / 8;
    const int grid_m = (M + 127) / 128;

    gather_kernel<1, 1><<<gat_blocks, 256>>>((const float4*)x, 32,
                                             aggH, aggL, nullptr, 64, 32,
                                             rowptr, csr, inv, M);
    gemm_f16<<<dim3(2, grid_m), 256>>>(aggH, aggL, 128, xH, xL, 128,
                                       W1H, h1, 256, h1H, h1L, 128,
                                       M, 256, 1);

    gather_kernel<2, 1><<<gat_blocks, 256>>>((const float4*)h1, 64,
                                             aggH, aggL, nullptr, 128, 64,
                                             rowptr, csr, inv, M);
    gemm_f16<<<dim3(2, grid_m), 256>>>(aggH, aggL, 256, h1H, h1L, 256,
                                       W2H, nullptr, 0, h2H, h2L, 128,
                                       M, 256, 1);

    gemm_f16<<<dim3(1, grid_m), 256>>>(h2H, h2L, 256, (const uint32_t*)nullptr, (const uint32_t*)nullptr, 0,
                                       W3H, zr, 128, nullptr, nullptr, 0,
                                       M, 96, 0);
    gather_kernel<1, 0><<<gat_blocks, 256>>>((const float4*)zr, 32,
                                             nullptr, nullptr, (float4*)agg3, 12, 12,
                                             rowptr, csr, inv, M);

    dim3 blk(32, 8);
    final_kernel<<<(M + 7) / 8, blk>>>(agg3, zr, out, M);
}

// round 11
// speedup vs baseline: 1.3022x; 1.0790x over previous
#include <cuda_runtime.h>
#include <cuda_fp16.h>
#include <cstdint>
#include <math_constants.h>

#define NNODES 50000
#define NEDGES 600000
#define C_IN   128
#define C_HID  256
#define C_OUT  47

__device__ __align__(128) float    g_zr  [(size_t)NNODES * 128];
__device__ __align__(128) float    g_agg3[(size_t)NNODES * 48];
__device__ __align__(128) float    g_inv [NNODES];
__device__ __align__(128) uint32_t g_aggH[(size_t)NNODES * 128];
__device__ __align__(128) uint32_t g_aggL[(size_t)NNODES * 128];
__device__ __align__(128) uint32_t g_xH  [(size_t)NNODES * 64];
__device__ __align__(128) uint32_t g_xL  [(size_t)NNODES * 64];
__device__ __align__(128) uint32_t g_h1H [(size_t)NNODES * 128];
__device__ __align__(128) uint32_t g_h1L [(size_t)NNODES * 128];
__device__ __align__(128) uint32_t g_h2H [(size_t)NNODES * 128];
__device__ __align__(128) uint32_t g_h2L [(size_t)NNODES * 128];
__device__ __align__(128) uint32_t g_W1H [256 * 128];
__device__ __align__(128) uint32_t g_W2H [256 * 256];
__device__ __align__(128) uint32_t g_W3H [96 * 128];
__device__ __align__(128) int      g_cnt [NNODES];
__device__ __align__(128) int      g_rowptr[NNODES + 1];
__device__ __align__(128) int      g_cursor[NNODES];
__device__ __align__(128) int      g_csr [NEDGES];
__device__ __align__(128) int      g_bsum[512];
__device__ int g_is64;

__device__ __forceinline__ void split2f(float a, float b, uint32_t& hi, uint32_t& lo) {
    __half2 h = __floats2half2_rn(a, b);
    float2 hf = __half22float2(h);
    __half2 l = __floats2half2_rn(a - hf.x, b - hf.y);
    hi = *reinterpret_cast<uint32_t*>(&h);
    lo = *reinterpret_cast<uint32_t*>(&l);
}
__device__ __forceinline__ uint32_t packh(float a, float b) {
    __half2 h = __floats2half2_rn(a, b);
    return *reinterpret_cast<uint32_t*>(&h);
}
__device__ __forceinline__ float2 h2f(uint32_t u) {
    __half2 h = *reinterpret_cast<__half2*>(&u);
    return __half22float2(h);
}

__device__ __forceinline__ long long get_idx(const void* ei, long long i, int is64) {
    if (is64) return ((const long long*)ei)[i];
    return (long long)((const int*)ei)[i];
}

__global__ void detect_kernel(const int* ei32) {
    int bad = 0;
    for (int i = 2 * threadIdx.x + 1; i < 4096; i += 512) bad |= ei32[i];
    int any = __syncthreads_or(bad);
    if (threadIdx.x == 0) g_is64 = (any == 0) ? 1 : 0;
}

__global__ void zero_int_kernel(int* p, int n) {
    int i = blockIdx.x * blockDim.x + threadIdx.x;
    if (i < n) p[i] = 0;
}

__global__ void hist_kernel(const void* __restrict__ ei, int E, int* __restrict__ cnt) {
    int e = blockIdx.x * blockDim.x + threadIdx.x;
    if (e >= E) return;
    int is64 = g_is64;
    long long d = get_idx(ei, (long long)E + e, is64);
    atomicAdd(&cnt[d], 1);
}

__global__ void blocksum_kernel(const int* __restrict__ cnt, int* __restrict__ bsum, int M) {
    __shared__ int s[8];
    int i = blockIdx.x * 256 + threadIdx.x;
    int v = (i < M) ? cnt[i] : 0;
#pragma unroll
    for (int o = 16; o > 0; o >>= 1) v += __shfl_xor_sync(0xffffffffu, v, o);
    if ((threadIdx.x & 31) == 0) s[threadIdx.x >> 5] = v;
    __syncthreads();
    if (threadIdx.x == 0) {
        int t = 0;
#pragma unroll
        for (int w = 0; w < 8; w++) t += s[w];
        bsum[blockIdx.x] = t;
    }
}

__global__ void scanb_kernel(int* bsum, int nb) {
    __shared__ int s[512];
    int t = threadIdx.x;
    int v = (t < nb) ? bsum[t] : 0;
    s[t] = v;
    __syncthreads();
    for (int off = 1; off < 512; off <<= 1) {
        int u = (t >= off) ? s[t - off] : 0;
        __syncthreads();
        s[t] += u;
        __syncthreads();
    }
    if (t < nb) bsum[t] = s[t] - v;
}

__global__ void scan_final_kernel(const int* __restrict__ cnt, const int* __restrict__ bsum,
                                  int* __restrict__ rowptr, int* __restrict__ cursor,
                                  float* __restrict__ inv, int M) {
    __shared__ int s[256];
    int t = threadIdx.x;
    int i = blockIdx.x * 256 + t;
    int c = (i < M) ? cnt[i] : 0;
    s[t] = c;
    __syncthreads();
    for (int off = 1; off < 256; off <<= 1) {
        int u = (t >= off) ? s[t - off] : 0;
        __syncthreads();
        s[t] += u;
        __syncthreads();
    }
    if (i < M) {
        int rp = bsum[blockIdx.x] + s[t] - c;
        rowptr[i] = rp;
        cursor[i] = rp;
        inv[i] = 1.0f / fmaxf((float)c, 1.0f);
        if (i == M - 1) rowptr[M] = rp + c;
    }
}

__global__ void fill_kernel(const void* __restrict__ ei, int E,
                            int* __restrict__ cursor, int* __restrict__ csr) {
    int e = blockIdx.x * blockDim.x + threadIdx.x;
    if (e >= E) return;
    int is64 = g_is64;
    long long s = get_idx(ei, e, is64);
    long long d = get_idx(ei, (long long)E + e, is64);
    int slot = atomicAdd(&cursor[d], 1);
    csr[slot] = (int)s;
}

__global__ void packw_kernel(const float* __restrict__ s1, int k1,
                             const float* __restrict__ s2, int k2,
                             uint32_t* __restrict__ H, uint32_t* __restrict__ L, int N) {
    int ktot = k1 + k2;
    int nu = ktot >> 1;
    int i = blockIdx.x * blockDim.x + threadIdx.x;
    if (i >= N * nu) return;
    int row = i / nu, j = i - row * nu;
    int f0 = 2 * j;
    float a, b;
    if (f0 < k1) { a = s1[(size_t)row * k1 + f0]; b = s1[(size_t)row * k1 + f0 + 1]; }
    else         { a = s2[(size_t)row * k2 + f0 - k1]; b = s2[(size_t)row * k2 + f0 - k1 + 1]; }
    if (L) {
        uint32_t hi, lo;
        split2f(a, b, hi, lo);
        H[i] = hi; L[i] = lo;
    } else {
        H[i] = packh(a, b);
    }
}

__global__ void packw3_kernel(const float* __restrict__ Wl3, const float* __restrict__ Wr3,
                              uint32_t* __restrict__ H) {
    int i = blockIdx.x * blockDim.x + threadIdx.x;
    if (i >= 96 * 128) return;
    int row = i >> 7, j = i & 127;
    float a = 0.f, b = 0.f;
    if (row < 47)      { a = Wl3[row * 256 + 2 * j]; b = Wl3[row * 256 + 2 * j + 1]; }
    else if (row < 94) { a = Wr3[(row - 47) * 256 + 2 * j]; b = Wr3[(row - 47) * 256 + 2 * j + 1]; }
    H[i] = packh(a, b);
}

// gather from packed fp16-hi source; fp32 accumulate; packed hi/lo output
template <int NACC>
__global__ void gather_h16(const uint2* __restrict__ src, int src_ld2,
                           uint32_t* __restrict__ dH, uint32_t* __restrict__ dL, int dst_ld,
                           const int* __restrict__ rowptr, const int* __restrict__ csr,
                           const float* __restrict__ inv, int M) {
    int node = blockIdx.x * (blockDim.x >> 5) + (threadIdx.x >> 5);
    if (node >= M) return;
    int lane = threadIdx.x & 31;
    int beg = rowptr[node], end = rowptr[node + 1];
    float s = inv[node];
    float4 acc[NACC];
#pragma unroll
    for (int i = 0; i < NACC; i++) acc[i] = make_float4(0.f, 0.f, 0.f, 0.f);
    int e = beg;
    for (; e + 1 < end; e += 2) {
        const uint2* r0 = src + (size_t)csr[e] * src_ld2;
        const uint2* r1 = src + (size_t)csr[e + 1] * src_ld2;
#pragma unroll
        for (int i = 0; i < NACC; i++) {
            uint2 p0 = r0[lane + 32 * i];
            uint2 p1 = r1[lane + 32 * i];
            float2 a0 = h2f(p0.x), b0 = h2f(p0.y);
            float2 a1 = h2f(p1.x), b1 = h2f(p1.y);
            acc[i].x += a0.x + a1.x; acc[i].y += a0.y + a1.y;
            acc[i].z += b0.x + b1.x; acc[i].w += b0.y + b1.y;
        }
    }
    if (e < end) {
        const uint2* r0 = src + (size_t)csr[e] * src_ld2;
#pragma unroll
        for (int i = 0; i < NACC; i++) {
            uint2 p0 = r0[lane + 32 * i];
            float2 a0 = h2f(p0.x), b0 = h2f(p0.y);
            acc[i].x += a0.x; acc[i].y += a0.y;
            acc[i].z += b0.x; acc[i].w += b0.y;
        }
    }
#pragma unroll
    for (int i = 0; i < NACC; i++) {
        float4 v = acc[i];
        v.x *= s; v.y *= s; v.z *= s; v.w *= s;
        uint32_t h0, l0, h1, l1;
        split2f(v.x, v.y, h0, l0);
        split2f(v.z, v.w, h1, l1);
        int col2 = (lane + 32 * i) * 2;
        *(uint2*)(dH + (size_t)node * dst_ld + col2) = make_uint2(h0, h1);
        *(uint2*)(dL + (size_t)node * dst_ld + col2) = make_uint2(l0, l1);
    }
}

// fp32 gather (layer 3): zr rows (ld 32 float4), cols 0..11 float4 -> agg3 (ld 12)
__global__ void gather_f32(const float4* __restrict__ src, int src_ld4,
                           float4* __restrict__ dF, int dst_ld, int nC4,
                           const int* __restrict__ rowptr, const int* __restrict__ csr,
                           const float* __restrict__ inv, int M) {
    int node = blockIdx.x * (blockDim.x >> 5) + (threadIdx.x >> 5);
    if (node >= M) return;
    int lane = threadIdx.x & 31;
    int beg = rowptr[node], end = rowptr[node + 1];
    float s = inv[node];
    float4 acc = make_float4(0.f, 0.f, 0.f, 0.f);
    bool act = lane < nC4;
    int e = beg;
    for (; e + 1 < end; e += 2) {
        if (act) {
            float4 v0 = src[(size_t)csr[e] * src_ld4 + lane];
            float4 v1 = src[(size_t)csr[e + 1] * src_ld4 + lane];
            acc.x += v0.x + v1.x; acc.y += v0.y + v1.y;
            acc.z += v0.z + v1.z; acc.w += v0.w + v1.w;
        }
    }
    if (e < end && act) {
        float4 v0 = src[(size_t)csr[e] * src_ld4 + lane];
        acc.x += v0.x; acc.y += v0.y; acc.z += v0.z; acc.w += v0.w;
    }
    if (act) {
        acc.x *= s; acc.y *= s; acc.z *= s; acc.w *= s;
        dF[(size_t)node * dst_ld + lane] = acc;
    }
}

#define BROW 12

__device__ __forceinline__ uint32_t smem_u32(const void* p) {
    uint32_t a;
    asm("{ .reg .u64 t; cvta.to.shared.u64 t, %1; cvt.u32.u64 %0, t; }" : "=r"(a) : "l"(p));
    return a;
}
__device__ __forceinline__ void cpa16(uint32_t dst, const void* src, int sz) {
    asm volatile("cp.async.cg.shared.global [%0], [%1], 16, %2;"
                 :: "r"(dst), "l"(src), "r"(sz) : "memory");
}
__device__ __forceinline__ void mma_f16(float* c, uint32_t a0, uint32_t a1, uint32_t a2, uint32_t a3,
                                        uint32_t b0, uint32_t b1) {
    asm volatile(
        "mma.sync.aligned.m16n8k16.row.col.f32.f16.f16.f32 "
        "{%0,%1,%2,%3}, {%4,%5,%6,%7}, {%8,%9}, {%0,%1,%2,%3};"
        : "+f"(c[0]), "+f"(c[1]), "+f"(c[2]), "+f"(c[3])
        : "r"(a0), "r"(a1), "r"(a2), "r"(a3), "r"(b0), "r"(b1));
}

__global__ void __launch_bounds__(256, 2)
gemm_f16(const uint32_t* __restrict__ A1H, const uint32_t* __restrict__ A1L, int K1,
         const uint32_t* __restrict__ A2H, const uint32_t* __restrict__ A2L, int K2,
         const uint32_t* __restrict__ BH,
         float* __restrict__ C, int ldc,
         uint32_t* __restrict__ CH, uint32_t* __restrict__ CL, int ldch,
         int M, int N, int do_relu) {
    __shared__ uint32_t sbuf[2][3][128 * BROW];

    const int tid = threadIdx.x;
    const int wid = tid >> 5;
    const int lid = tid & 31;
    const int gID = lid >> 2;
    const int tig = lid & 3;
    const int warp_m = wid & 3;
    const int warp_n = wid >> 2;
    const int m_base = blockIdx.y * 128;
    const int n_base = blockIdx.x * 128;
    const int K = K1 + K2;
    const int nchunks = K >> 4;
    const int ldb = K >> 1;
    const int k1u = K1 >> 1;
    const uint32_t sb = smem_u32(&sbuf[0][0][0]);

    const int crow = tid >> 1;
    const int chalf = tid & 1;
    const int mg = m_base + crow;
    const int ng = n_base + crow;
    const int szA = (mg < M) ? 16 : 0;
    const int szB = (ng < N) ? 16 : 0;
    const uint32_t doff = (uint32_t)(crow * BROW + chalf * 4) * 4;

    float acc[2][8][4];
#pragma unroll
    for (int mi = 0; mi < 2; mi++)
#pragma unroll
        for (int ni = 0; ni < 8; ni++)
#pragma unroll
            for (int j = 0; j < 4; j++) acc[mi][ni][j] = 0.f;

    auto copy_chunk = [&](int kc, int s) {
        int ku = (kc << 3) + chalf * 4;
        const uint32_t *ah, *al;
        if (ku < k1u) {
            ah = A1H + (size_t)mg * k1u + ku;
            al = A1L + (size_t)mg * k1u + ku;
        } else {
            int k2u = K2 >> 1;
            ah = A2H + (size_t)mg * k2u + (ku - k1u);
            al = A2L + (size_t)mg * k2u + (ku - k1u);
        }
        uint32_t base = sb + (uint32_t)(s * 3) * (128 * BROW * 4);
        cpa16(base + doff,                      ah, szA);
        cpa16(base + 128 * BROW * 4 + doff,     al, szA);
        const uint32_t* bh = BH + (size_t)ng * ldb + ku;
        cpa16(base + 2 * 128 * BROW * 4 + doff, bh, szB);
    };

    copy_chunk(0, 0);
    asm volatile("cp.async.commit_group;" ::: "memory");

    for (int kc = 0; kc < nchunks; kc++) {
        int s = kc & 1;
        if (kc + 1 < nchunks) {
            copy_chunk(kc + 1, (kc + 1) & 1);
            asm volatile("cp.async.commit_group;" ::: "memory");
            asm volatile("cp.async.wait_group 1;" ::: "memory");
        } else {
            asm volatile("cp.async.wait_group 0;" ::: "memory");
        }
        __syncthreads();

        const uint32_t* Ah = sbuf[s][0];
        const uint32_t* Al = sbuf[s][1];
        const uint32_t* Bh = sbuf[s][2];

        uint32_t ah[2][4], al[2][4];
#pragma unroll
        for (int mi = 0; mi < 2; mi++) {
            int rm = warp_m * 32 + mi * 16;
            int r0 = (rm + gID) * BROW + tig;
            int r1 = (rm + gID + 8) * BROW + tig;
            ah[mi][0] = Ah[r0];     ah[mi][1] = Ah[r1];
            ah[mi][2] = Ah[r0 + 4]; ah[mi][3] = Ah[r1 + 4];
            al[mi][0] = Al[r0];     al[mi][1] = Al[r1];
            al[mi][2] = Al[r0 + 4]; al[mi][3] = Al[r1 + 4];
        }
#pragma unroll
        for (int ni = 0; ni < 8; ni++) {
            int nn = warp_n * 64 + ni * 8 + gID;
            int o = nn * BROW + tig;
            uint32_t bh0 = Bh[o], bh1 = Bh[o + 4];
#pragma unroll
            for (int mi = 0; mi < 2; mi++) {
                mma_f16(acc[mi][ni], ah[mi][0], ah[mi][1], ah[mi][2], ah[mi][3], bh0, bh1);
                mma_f16(acc[mi][ni], al[mi][0], al[mi][1], al[mi][2], al[mi][3], bh0, bh1);
            }
        }
        __syncthreads();
    }

#pragma unroll
    for (int mi = 0; mi < 2; mi++) {
#pragma unroll
        for (int ni = 0; ni < 8; ni++) {
            int col = n_base + warp_n * 64 + ni * 8 + 2 * tig;
            if (col >= N) continue;
            int r0 = m_base + warp_m * 32 + mi * 16 + gID;
            int r1 = r0 + 8;
            float2 v0 = make_float2(acc[mi][ni][0], acc[mi][ni][1]);
            float2 v1 = make_float2(acc[mi][ni][2], acc[mi][ni][3]);
            if (do_relu) {
                v0.x = fmaxf(v0.x, 0.f); v0.y = fmaxf(v0.y, 0.f);
                v1.x = fmaxf(v1.x, 0.f); v1.y = fmaxf(v1.y, 0.f);
            }
            if (r0 < M) {
                if (C) *(float2*)(C + (size_t)r0 * ldc + col) = v0;
                if (CH) {
                    uint32_t hi, lo;
                    split2f(v0.x, v0.y, hi, lo);
                    CH[(size_t)r0 * ldch + (col >> 1)] = hi;
                    CL[(size_t)r0 * ldch + (col >> 1)] = lo;
                }
            }
            if (r1 < M) {
                if (C) *(float2*)(C + (size_t)r1 * ldc + col) = v1;
                if (CH) {
                    uint32_t hi, lo;
                    split2f(v1.x, v1.y, hi, lo);
                    CH[(size_t)r1 * ldch + (col >> 1)] = hi;
                    CL[(size_t)r1 * ldch + (col >> 1)] = lo;
                }
            }
        }
    }
}

__global__ void final_kernel(const float* __restrict__ agg3, const float* __restrict__ zr,
                             float* __restrict__ out, int M) {
    int m = blockIdx.x * blockDim.y + threadIdx.y;
    if (m >= M) return;
    int lane = threadIdx.x;
    float v1 = -CUDART_INF_F, v2 = -CUDART_INF_F;
    if (lane < 47)
        v1 = agg3[(size_t)m * 48 + lane] + zr[(size_t)m * 128 + 47 + lane];
    int c2 = lane + 32;
    if (c2 < 47)
        v2 = agg3[(size_t)m * 48 + c2] + zr[(size_t)m * 128 + 47 + c2];
    float mx = fmaxf(v1, v2);
#pragma unroll
    for (int o = 16; o > 0; o >>= 1) mx = fmaxf(mx, __shfl_xor_sync(0xffffffffu, mx, o));
    float s = 0.f;
    if (lane < 47) s += expf(v1 - mx);
    if (c2 < 47)   s += expf(v2 - mx);
#pragma unroll
    for (int o = 16; o > 0; o >>= 1) s += __shfl_xor_sync(0xffffffffu, s, o);
    float lse = logf(s);
    if (lane < 47) out[(size_t)m * 47 + lane] = v1 - mx - lse;
    if (c2 < 47)   out[(size_t)m * 47 + c2]   = v2 - mx - lse;
}

extern "C" void kernel_launch(void* const* d_in, const int* in_sizes, int n_in,
                              void* d_out, int out_size) {
    const float* x   = (const float*)d_in[0];
    const float* Wl1 = (const float*)d_in[1];
    const float* Wr1 = (const float*)d_in[2];
    const float* Wl2 = (const float*)d_in[3];
    const float* Wr2 = (const float*)d_in[4];
    const float* Wl3 = (const float*)d_in[5];
    const float* Wr3 = (const float*)d_in[6];
    const void*  ei  = d_in[7];
    const int E = in_sizes[7] / 2;
    const int M = in_sizes[0] / C_IN;
    float* out = (float*)d_out;

    float *zr, *agg3, *inv;
    uint32_t *aggH, *aggL, *xH, *xL, *h1H, *h1L, *h2H, *h2L;
    uint32_t *W1H, *W2H, *W3H;
    int *cnt, *rowptr, *cursor, *csr, *bsum;
    cudaGetSymbolAddress((void**)&zr,     g_zr);
    cudaGetSymbolAddress((void**)&agg3,   g_agg3);
    cudaGetSymbolAddress((void**)&inv,    g_inv);
    cudaGetSymbolAddress((void**)&aggH,   g_aggH);
    cudaGetSymbolAddress((void**)&aggL,   g_aggL);
    cudaGetSymbolAddress((void**)&xH,     g_xH);
    cudaGetSymbolAddress((void**)&xL,     g_xL);
    cudaGetSymbolAddress((void**)&h1H,    g_h1H);
    cudaGetSymbolAddress((void**)&h1L,    g_h1L);
    cudaGetSymbolAddress((void**)&h2H,    g_h2H);
    cudaGetSymbolAddress((void**)&h2L,    g_h2L);
    cudaGetSymbolAddress((void**)&W1H,    g_W1H);
    cudaGetSymbolAddress((void**)&W2H,    g_W2H);
    cudaGetSymbolAddress((void**)&W3H,    g_W3H);
    cudaGetSymbolAddress((void**)&cnt,    g_cnt);
    cudaGetSymbolAddress((void**)&rowptr, g_rowptr);
    cudaGetSymbolAddress((void**)&cursor, g_cursor);
    cudaGetSymbolAddress((void**)&csr,    g_csr);
    cudaGetSymbolAddress((void**)&bsum,   g_bsum);

    detect_kernel<<<1, 256>>>((const int*)ei);

    const int nb = (M + 255) / 256;
    zero_int_kernel<<<nb, 256>>>(cnt, M);
    hist_kernel<<<(E + 255) / 256, 256>>>(ei, E, cnt);
    blocksum_kernel<<<nb, 256>>>(cnt, bsum, M);
    scanb_kernel<<<1, 512>>>(bsum, nb);
    scan_final_kernel<<<nb, 256>>>(cnt, bsum, rowptr, cursor, inv, M);
    fill_kernel<<<(E + 255) / 256, 256>>>(ei, E, cursor, csr);

    packw_kernel<<<(256 * 128 + 255) / 256, 256>>>(Wl1, 128, Wr1, 128, W1H, nullptr, 256);
    packw_kernel<<<(256 * 256 + 255) / 256, 256>>>(Wl2, 256, Wr2, 256, W2H, nullptr, 256);
    packw3_kernel<<<(96 * 128 + 255) / 256, 256>>>(Wl3, Wr3, W3H);
    packw_kernel<<<((M * 64) + 255) / 256, 256>>>(x, 128, (const float*)nullptr, 0, xH, xL, M);

    const int gat_blocks = (M + 7) / 8;
    const int grid_m = (M + 127) / 128;

    // layer 1: gather fp16-hi of x -> agg packed; GEMM writes h1 packed only
    gather_h16<1><<<gat_blocks, 256>>>((const uint2*)xH, 32,
                                       aggH, aggL, 64,
                                       rowptr, csr, inv, M);
    gemm_f16<<<dim3(2, grid_m), 256>>>(aggH, aggL, 128, xH, xL, 128,
                                       W1H, nullptr, 0, h1H, h1L, 128,
                                       M, 256, 1);

    // layer 2: gather fp16-hi of h1 -> agg packed; GEMM writes h2 packed only
    gather_h16<2><<<gat_blocks, 256>>>((const uint2*)h1H, 64,
                                       aggH, aggL, 128,
                                       rowptr, csr, inv, M);
    gemm_f16<<<dim3(2, grid_m), 256>>>(aggH, aggL, 256, h1H, h1L, 256,
                                       W2H, nullptr, 0, h2H, h2L, 128,
                                       M, 256, 1);

    // layer 3: transform-first (fp32 zr), fp32 gather, log_softmax
    gemm_f16<<<dim3(1, grid_m), 256>>>(h2H, h2L, 256, (const uint32_t*)nullptr, (const uint32_t*)nullptr, 0,
                                       W3H, zr, 128, nullptr, nullptr, 0,
                                       M, 96, 0);
    gather_f32<<<gat_blocks, 256>>>((const float4*)zr, 32,
                                    (float4*)agg3, 12, 12,
                                    rowptr, csr, inv, M);

    dim3 blk(32, 8);
    final_kernel<<<(M + 7) / 8, blk>>>(agg3, zr, out, M);
}

// round 12
// speedup vs baseline: 1.6947x; 1.3014x over previous
#include <cuda_runtime.h>
#include <cuda_fp16.h>
#include <cstdint>
#include <math_constants.h>

#define NNODES 50000
#define NEDGES 600000
#define C_IN   128
#define C_HID  256
#define C_OUT  47

__device__ __align__(128) float    g_zr  [(size_t)NNODES * 128];
__device__ __align__(128) float    g_agg3[(size_t)NNODES * 48];
__device__ __align__(128) float    g_inv [NNODES];
__device__ __align__(128) uint32_t g_aggH[(size_t)NNODES * 128];
__device__ __align__(128) uint32_t g_xH  [(size_t)NNODES * 64];
__device__ __align__(128) uint32_t g_h1H [(size_t)NNODES * 128];
__device__ __align__(128) uint32_t g_h2H [(size_t)NNODES * 128];
__device__ __align__(128) uint32_t g_W1H [256 * 128];
__device__ __align__(128) uint32_t g_W2H [256 * 256];
__device__ __align__(128) uint32_t g_W3H [96 * 128];
__device__ __align__(128) int      g_cnt [NNODES];
__device__ __align__(128) int      g_rowptr[NNODES + 1];
__device__ __align__(128) int      g_cursor[NNODES];
__device__ __align__(128) int      g_csr [NEDGES];
__device__ __align__(128) int      g_bsum[512];
__device__ int g_is64;

__device__ __forceinline__ uint32_t packh(float a, float b) {
    __half2 h = __floats2half2_rn(a, b);
    return *reinterpret_cast<uint32_t*>(&h);
}
__device__ __forceinline__ float2 h2f(uint32_t u) {
    __half2 h = *reinterpret_cast<__half2*>(&u);
    return __half22float2(h);
}

__device__ __forceinline__ long long get_idx(const void* ei, long long i, int is64) {
    if (is64) return ((const long long*)ei)[i];
    return (long long)((const int*)ei)[i];
}

__global__ void detect_kernel(const int* ei32) {
    int bad = 0;
    for (int i = 2 * threadIdx.x + 1; i < 4096; i += 512) bad |= ei32[i];
    int any = __syncthreads_or(bad);
    if (threadIdx.x == 0) g_is64 = (any == 0) ? 1 : 0;
}

__global__ void zero_int_kernel(int* p, int n) {
    int i = blockIdx.x * blockDim.x + threadIdx.x;
    if (i < n) p[i] = 0;
}

__global__ void hist_kernel(const void* __restrict__ ei, int E, int* __restrict__ cnt) {
    int e = blockIdx.x * blockDim.x + threadIdx.x;
    if (e >= E) return;
    int is64 = g_is64;
    long long d = get_idx(ei, (long long)E + e, is64);
    atomicAdd(&cnt[d], 1);
}

__global__ void blocksum_kernel(const int* __restrict__ cnt, int* __restrict__ bsum, int M) {
    __shared__ int s[8];
    int i = blockIdx.x * 256 + threadIdx.x;
    int v = (i < M) ? cnt[i] : 0;
#pragma unroll
    for (int o = 16; o > 0; o >>= 1) v += __shfl_xor_sync(0xffffffffu, v, o);
    if ((threadIdx.x & 31) == 0) s[threadIdx.x >> 5] = v;
    __syncthreads();
    if (threadIdx.x == 0) {
        int t = 0;
#pragma unroll
        for (int w = 0; w < 8; w++) t += s[w];
        bsum[blockIdx.x] = t;
    }
}

__global__ void scanb_kernel(int* bsum, int nb) {
    __shared__ int s[512];
    int t = threadIdx.x;
    int v = (t < nb) ? bsum[t] : 0;
    s[t] = v;
    __syncthreads();
    for (int off = 1; off < 512; off <<= 1) {
        int u = (t >= off) ? s[t - off] : 0;
        __syncthreads();
        s[t] += u;
        __syncthreads();
    }
    if (t < nb) bsum[t] = s[t] - v;
}

__global__ void scan_final_kernel(const int* __restrict__ cnt, const int* __restrict__ bsum,
                                  int* __restrict__ rowptr, int* __restrict__ cursor,
                                  float* __restrict__ inv, int M) {
    __shared__ int s[256];
    int t = threadIdx.x;
    int i = blockIdx.x * 256 + t;
    int c = (i < M) ? cnt[i] : 0;
    s[t] = c;
    __syncthreads();
    for (int off = 1; off < 256; off <<= 1) {
        int u = (t >= off) ? s[t - off] : 0;
        __syncthreads();
        s[t] += u;
        __syncthreads();
    }
    if (i < M) {
        int rp = bsum[blockIdx.x] + s[t] - c;
        rowptr[i] = rp;
        cursor[i] = rp;
        inv[i] = 1.0f / fmaxf((float)c, 1.0f);
        if (i == M - 1) rowptr[M] = rp + c;
    }
}

__global__ void fill_kernel(const void* __restrict__ ei, int E,
                            int* __restrict__ cursor, int* __restrict__ csr) {
    int e = blockIdx.x * blockDim.x + threadIdx.x;
    if (e >= E) return;
    int is64 = g_is64;
    long long s = get_idx(ei, e, is64);
    long long d = get_idx(ei, (long long)E + e, is64);
    int slot = atomicAdd(&cursor[d], 1);
    csr[slot] = (int)s;
}

__global__ void packw_kernel(const float* __restrict__ s1, int k1,
                             const float* __restrict__ s2, int k2,
                             uint32_t* __restrict__ H, int N) {
    int ktot = k1 + k2;
    int nu = ktot >> 1;
    int i = blockIdx.x * blockDim.x + threadIdx.x;
    if (i >= N * nu) return;
    int row = i / nu, j = i - row * nu;
    int f0 = 2 * j;
    float a, b;
    if (f0 < k1) { a = s1[(size_t)row * k1 + f0]; b = s1[(size_t)row * k1 + f0 + 1]; }
    else         { a = s2[(size_t)row * k2 + f0 - k1]; b = s2[(size_t)row * k2 + f0 - k1 + 1]; }
    H[i] = packh(a, b);
}

__global__ void packw3_kernel(const float* __restrict__ Wl3, const float* __restrict__ Wr3,
                              uint32_t* __restrict__ H) {
    int i = blockIdx.x * blockDim.x + threadIdx.x;
    if (i >= 96 * 128) return;
    int row = i >> 7, j = i & 127;
    float a = 0.f, b = 0.f;
    if (row < 47)      { a = Wl3[row * 256 + 2 * j]; b = Wl3[row * 256 + 2 * j + 1]; }
    else if (row < 94) { a = Wr3[(row - 47) * 256 + 2 * j]; b = Wr3[(row - 47) * 256 + 2 * j + 1]; }
    H[i] = packh(a, b);
}

// gather from packed fp16 source; fp32 accumulate; packed fp16 output
template <int NACC>
__global__ void gather_h16(const uint2* __restrict__ src, int src_ld2,
                           uint32_t* __restrict__ dH, int dst_ld,
                           const int* __restrict__ rowptr, const int* __restrict__ csr,
                           const float* __restrict__ inv, int M) {
    int node = blockIdx.x * (blockDim.x >> 5) + (threadIdx.x >> 5);
    if (node >= M) return;
    int lane = threadIdx.x & 31;
    int beg = rowptr[node], end = rowptr[node + 1];
    float s = inv[node];
    float4 acc[NACC];
#pragma unroll
    for (int i = 0; i < NACC; i++) acc[i] = make_float4(0.f, 0.f, 0.f, 0.f);
    int e = beg;
    for (; e + 1 < end; e += 2) {
        const uint2* r0 = src + (size_t)csr[e] * src_ld2;
        const uint2* r1 = src + (size_t)csr[e + 1] * src_ld2;
#pragma unroll
        for (int i = 0; i < NACC; i++) {
            uint2 p0 = r0[lane + 32 * i];
            uint2 p1 = r1[lane + 32 * i];
            float2 a0 = h2f(p0.x), b0 = h2f(p0.y);
            float2 a1 = h2f(p1.x), b1 = h2f(p1.y);
            acc[i].x += a0.x + a1.x; acc[i].y += a0.y + a1.y;
            acc[i].z += b0.x + b1.x; acc[i].w += b0.y + b1.y;
        }
    }
    if (e < end) {
        const uint2* r0 = src + (size_t)csr[e] * src_ld2;
#pragma unroll
        for (int i = 0; i < NACC; i++) {
            uint2 p0 = r0[lane + 32 * i];
            float2 a0 = h2f(p0.x), b0 = h2f(p0.y);
            acc[i].x += a0.x; acc[i].y += a0.y;
            acc[i].z += b0.x; acc[i].w += b0.y;
        }
    }
#pragma unroll
    for (int i = 0; i < NACC; i++) {
        float4 v = acc[i];
        v.x *= s; v.y *= s; v.z *= s; v.w *= s;
        int col2 = (lane + 32 * i) * 2;
        *(uint2*)(dH + (size_t)node * dst_ld + col2) =
            make_uint2(packh(v.x, v.y), packh(v.z, v.w));
    }
}

// fp32 gather (layer 3)
__global__ void gather_f32(const float4* __restrict__ src, int src_ld4,
                           float4* __restrict__ dF, int dst_ld, int nC4,
                           const int* __restrict__ rowptr, const int* __restrict__ csr,
                           const float* __restrict__ inv, int M) {
    int node = blockIdx.x * (blockDim.x >> 5) + (threadIdx.x >> 5);
    if (node >= M) return;
    int lane = threadIdx.x & 31;
    int beg = rowptr[node], end = rowptr[node + 1];
    float s = inv[node];
    float4 acc = make_float4(0.f, 0.f, 0.f, 0.f);
    bool act = lane < nC4;
    int e = beg;
    for (; e + 1 < end; e += 2) {
        if (act) {
            float4 v0 = src[(size_t)csr[e] * src_ld4 + lane];
            float4 v1 = src[(size_t)csr[e + 1] * src_ld4 + lane];
            acc.x += v0.x + v1.x; acc.y += v0.y + v1.y;
            acc.z += v0.z + v1.z; acc.w += v0.w + v1.w;
        }
    }
    if (e < end && act) {
        float4 v0 = src[(size_t)csr[e] * src_ld4 + lane];
        acc.x += v0.x; acc.y += v0.y; acc.z += v0.z; acc.w += v0.w;
    }
    if (act) {
        acc.x *= s; acc.y *= s; acc.z *= s; acc.w *= s;
        dF[(size_t)node * dst_ld + lane] = acc;
    }
}

#define BROW 12

__device__ __forceinline__ uint32_t smem_u32(const void* p) {
    uint32_t a;
    asm("{ .reg .u64 t; cvta.to.shared.u64 t, %1; cvt.u32.u64 %0, t; }" : "=r"(a) : "l"(p));
    return a;
}
__device__ __forceinline__ void cpa16(uint32_t dst, const void* src, int sz) {
    asm volatile("cp.async.cg.shared.global [%0], [%1], 16, %2;"
                 :: "r"(dst), "l"(src), "r"(sz) : "memory");
}
__device__ __forceinline__ void mma_f16(float* c, uint32_t a0, uint32_t a1, uint32_t a2, uint32_t a3,
                                        uint32_t b0, uint32_t b1) {
    asm volatile(
        "mma.sync.aligned.m16n8k16.row.col.f32.f16.f16.f32 "
        "{%0,%1,%2,%3}, {%4,%5,%6,%7}, {%8,%9}, {%0,%1,%2,%3};"
        : "+f"(c[0]), "+f"(c[1]), "+f"(c[2]), "+f"(c[3])
        : "r"(a0), "r"(a1), "r"(a2), "r"(a3), "r"(b0), "r"(b1));
}

// single-term fp16 GEMM: D = A*B, A = [A1 | A2] packed fp16, B packed fp16
__global__ void __launch_bounds__(256, 2)
gemm_f16(const uint32_t* __restrict__ A1H, int K1,
         const uint32_t* __restrict__ A2H, int K2,
         const uint32_t* __restrict__ BH,
         float* __restrict__ C, int ldc,
         uint32_t* __restrict__ CH, int ldch,
         int M, int N, int do_relu) {
    __shared__ uint32_t sbuf[2][2][128 * BROW];

    const int tid = threadIdx.x;
    const int wid = tid >> 5;
    const int lid = tid & 31;
    const int gID = lid >> 2;
    const int tig = lid & 3;
    const int warp_m = wid & 3;
    const int warp_n = wid >> 2;
    const int m_base = blockIdx.y * 128;
    const int n_base = blockIdx.x * 128;
    const int K = K1 + K2;
    const int nchunks = K >> 4;
    const int ldb = K >> 1;
    const int k1u = K1 >> 1;
    const uint32_t sb = smem_u32(&sbuf[0][0][0]);

    const int crow = tid >> 1;
    const int chalf = tid & 1;
    const int mg = m_base + crow;
    const int ng = n_base + crow;
    const int szA = (mg < M) ? 16 : 0;
    const int szB = (ng < N) ? 16 : 0;
    const uint32_t doff = (uint32_t)(crow * BROW + chalf * 4) * 4;

    float acc[2][8][4];
#pragma unroll
    for (int mi = 0; mi < 2; mi++)
#pragma unroll
        for (int ni = 0; ni < 8; ni++)
#pragma unroll
            for (int j = 0; j < 4; j++) acc[mi][ni][j] = 0.f;

    auto copy_chunk = [&](int kc, int s) {
        int ku = (kc << 3) + chalf * 4;
        const uint32_t* ah;
        if (ku < k1u) ah = A1H + (size_t)mg * k1u + ku;
        else          ah = A2H + (size_t)mg * (K2 >> 1) + (ku - k1u);
        uint32_t base = sb + (uint32_t)(s * 2) * (128 * BROW * 4);
        cpa16(base + doff,                    ah, szA);
        const uint32_t* bh = BH + (size_t)ng * ldb + ku;
        cpa16(base + 128 * BROW * 4 + doff,   bh, szB);
    };

    copy_chunk(0, 0);
    asm volatile("cp.async.commit_group;" ::: "memory");

    for (int kc = 0; kc < nchunks; kc++) {
        int s = kc & 1;
        if (kc + 1 < nchunks) {
            copy_chunk(kc + 1, (kc + 1) & 1);
            asm volatile("cp.async.commit_group;" ::: "memory");
            asm volatile("cp.async.wait_group 1;" ::: "memory");
        } else {
            asm volatile("cp.async.wait_group 0;" ::: "memory");
        }
        __syncthreads();

        const uint32_t* Ah = sbuf[s][0];
        const uint32_t* Bh = sbuf[s][1];

        uint32_t ah[2][4];
#pragma unroll
        for (int mi = 0; mi < 2; mi++) {
            int rm = warp_m * 32 + mi * 16;
            int r0 = (rm + gID) * BROW + tig;
            int r1 = (rm + gID + 8) * BROW + tig;
            ah[mi][0] = Ah[r0];     ah[mi][1] = Ah[r1];
            ah[mi][2] = Ah[r0 + 4]; ah[mi][3] = Ah[r1 + 4];
        }
#pragma unroll
        for (int ni = 0; ni < 8; ni++) {
            int nn = warp_n * 64 + ni * 8 + gID;
            int o = nn * BROW + tig;
            uint32_t bh0 = Bh[o], bh1 = Bh[o + 4];
#pragma unroll
            for (int mi = 0; mi < 2; mi++) {
                mma_f16(acc[mi][ni], ah[mi][0], ah[mi][1], ah[mi][2], ah[mi][3], bh0, bh1);
            }
        }
        __syncthreads();
    }

#pragma unroll
    for (int mi = 0; mi < 2; mi++) {
#pragma unroll
        for (int ni = 0; ni < 8; ni++) {
            int col = n_base + warp_n * 64 + ni * 8 + 2 * tig;
            if (col >= N) continue;
            int r0 = m_base + warp_m * 32 + mi * 16 + gID;
            int r1 = r0 + 8;
            float2 v0 = make_float2(acc[mi][ni][0], acc[mi][ni][1]);
            float2 v1 = make_float2(acc[mi][ni][2], acc[mi][ni][3]);
            if (do_relu) {
                v0.x = fmaxf(v0.x, 0.f); v0.y = fmaxf(v0.y, 0.f);
                v1.x = fmaxf(v1.x, 0.f); v1.y = fmaxf(v1.y, 0.f);
            }
            if (r0 < M) {
                if (C)  *(float2*)(C + (size_t)r0 * ldc + col) = v0;
                if (CH) CH[(size_t)r0 * ldch + (col >> 1)] = packh(v0.x, v0.y);
            }
            if (r1 < M) {
                if (C)  *(float2*)(C + (size_t)r1 * ldc + col) = v1;
                if (CH) CH[(size_t)r1 * ldch + (col >> 1)] = packh(v1.x, v1.y);
            }
        }
    }
}

__global__ void final_kernel(const float* __restrict__ agg3, const float* __restrict__ zr,
                             float* __restrict__ out, int M) {
    int m = blockIdx.x * blockDim.y + threadIdx.y;
    if (m >= M) return;
    int lane = threadIdx.x;
    float v1 = -CUDART_INF_F, v2 = -CUDART_INF_F;
    if (lane < 47)
        v1 = agg3[(size_t)m * 48 + lane] + zr[(size_t)m * 128 + 47 + lane];
    int c2 = lane + 32;
    if (c2 < 47)
        v2 = agg3[(size_t)m * 48 + c2] + zr[(size_t)m * 128 + 47 + c2];
    float mx = fmaxf(v1, v2);
#pragma unroll
    for (int o = 16; o > 0; o >>= 1) mx = fmaxf(mx, __shfl_xor_sync(0xffffffffu, mx, o));
    float s = 0.f;
    if (lane < 47) s += expf(v1 - mx);
    if (c2 < 47)   s += expf(v2 - mx);
#pragma unroll
    for (int o = 16; o > 0; o >>= 1) s += __shfl_xor_sync(0xffffffffu, s, o);
    float lse = logf(s);
    if (lane < 47) out[(size_t)m * 47 + lane] = v1 - mx - lse;
    if (c2 < 47)   out[(size_t)m * 47 + c2]   = v2 - mx - lse;
}

extern "C" void kernel_launch(void* const* d_in, const int* in_sizes, int n_in,
                              void* d_out, int out_size) {
    const float* x   = (const float*)d_in[0];
    const float* Wl1 = (const float*)d_in[1];
    const float* Wr1 = (const float*)d_in[2];
    const float* Wl2 = (const float*)d_in[3];
    const float* Wr2 = (const float*)d_in[4];
    const float* Wl3 = (const float*)d_in[5];
    const float* Wr3 = (const float*)d_in[6];
    const void*  ei  = d_in[7];
    const int E = in_sizes[7] / 2;
    const int M = in_sizes[0] / C_IN;
    float* out = (float*)d_out;

    float *zr, *agg3, *inv;
    uint32_t *aggH, *xH, *h1H, *h2H;
    uint32_t *W1H, *W2H, *W3H;
    int *cnt, *rowptr, *cursor, *csr, *bsum;
    cudaGetSymbolAddress((void**)&zr,     g_zr);
    cudaGetSymbolAddress((void**)&agg3,   g_agg3);
    cudaGetSymbolAddress((void**)&inv,    g_inv);
    cudaGetSymbolAddress((void**)&aggH,   g_aggH);
    cudaGetSymbolAddress((void**)&xH,     g_xH);
    cudaGetSymbolAddress((void**)&h1H,    g_h1H);
    cudaGetSymbolAddress((void**)&h2H,    g_h2H);
    cudaGetSymbolAddress((void**)&W1H,    g_W1H);
    cudaGetSymbolAddress((void**)&W2H,    g_W2H);
    cudaGetSymbolAddress((void**)&W3H,    g_W3H);
    cudaGetSymbolAddress((void**)&cnt,    g_cnt);
    cudaGetSymbolAddress((void**)&rowptr, g_rowptr);
    cudaGetSymbolAddress((void**)&cursor, g_cursor);
    cudaGetSymbolAddress((void**)&csr,    g_csr);
    cudaGetSymbolAddress((void**)&bsum,   g_bsum);

    detect_kernel<<<1, 256>>>((const int*)ei);

    const int nb = (M + 255) / 256;
    zero_int_kernel<<<nb, 256>>>(cnt, M);
    hist_kernel<<<(E + 255) / 256, 256>>>(ei, E, cnt);
    blocksum_kernel<<<nb, 256>>>(cnt, bsum, M);
    scanb_kernel<<<1, 512>>>(bsum, nb);
    scan_final_kernel<<<nb, 256>>>(cnt, bsum, rowptr, cursor, inv, M);
    fill_kernel<<<(E + 255) / 256, 256>>>(ei, E, cursor, csr);

    packw_kernel<<<(256 * 128 + 255) / 256, 256>>>(Wl1, 128, Wr1, 128, W1H, 256);
    packw_kernel<<<(256 * 256 + 255) / 256, 256>>>(Wl2, 256, Wr2, 256, W2H, 256);
    packw3_kernel<<<(96 * 128 + 255) / 256, 256>>>(Wl3, Wr3, W3H);
    packw_kernel<<<((M * 64) + 255) / 256, 256>>>(x, 128, (const float*)nullptr, 0, xH, M);

    const int gat_blocks = (M + 7) / 8;
    const int grid_m = (M + 127) / 128;

    // layer 1
    gather_h16<1><<<gat_blocks, 256>>>((const uint2*)xH, 32,
                                       aggH, 64, rowptr, csr, inv, M);
    gemm_f16<<<dim3(2, grid_m), 256>>>(aggH, 128, xH, 128,
                                       W1H, nullptr, 0, h1H, 128,
                                       M, 256, 1);

    // layer 2
    gather_h16<2><<<gat_blocks, 256>>>((const uint2*)h1H, 64,
                                       aggH, 128, rowptr, csr, inv, M);
    gemm_f16<<<dim3(2, grid_m), 256>>>(aggH, 256, h1H, 256,
                                       W2H, nullptr, 0, h2H, 128,
                                       M, 256, 1);

    // layer 3: transform-first, fp32 zr, fp32 gather, log_softmax
    gemm_f16<<<dim3(1, grid_m), 256>>>(h2H, 256, (const uint32_t*)nullptr, 0,
                                       W3H, zr, 128, nullptr, 0,
                                       M, 96, 0);
    gather_f32<<<gat_blocks, 256>>>((const float4*)zr, 32,
                                    (float4*)agg3, 12, 12,
                                    rowptr, csr, inv, M);

    dim3 blk(32, 8);
    final_kernel<<<(M + 7) / 8, blk>>>(agg3, zr, out, M);
}

// round 13
// speedup vs baseline: 1.7361x; 1.0244x over previous
#include <cuda_runtime.h>
#include <cuda_fp16.h>
#include <cstdint>
#include <math_constants.h>

#define NNODES 50000
#define NEDGES 600000
#define C_IN   128
#define C_HID  256
#define C_OUT  47

__device__ __align__(128) float    g_inv [NNODES];
__device__ __align__(128) uint32_t g_aggH[(size_t)NNODES * 128];
__device__ __align__(128) uint32_t g_xH  [(size_t)NNODES * 64];
__device__ __align__(128) uint32_t g_h1H [(size_t)NNODES * 128];
__device__ __align__(128) uint32_t g_h2H [(size_t)NNODES * 128];
__device__ __align__(128) uint32_t g_zrH [(size_t)NNODES * 48];
__device__ __align__(128) uint32_t g_W1H [256 * 128];
__device__ __align__(128) uint32_t g_W2H [256 * 256];
__device__ __align__(128) uint32_t g_W3H [96 * 128];
__device__ __align__(128) int      g_cnt [NNODES];
__device__ __align__(128) int      g_rowptr[NNODES + 1];
__device__ __align__(128) int      g_cursor[NNODES];
__device__ __align__(128) int      g_csr [NEDGES];
__device__ __align__(128) int      g_bsum[512];
__device__ int g_is64;

__device__ __forceinline__ uint32_t packh(float a, float b) {
    __half2 h = __floats2half2_rn(a, b);
    return *reinterpret_cast<uint32_t*>(&h);
}
__device__ __forceinline__ float2 h2f(uint32_t u) {
    __half2 h = *reinterpret_cast<__half2*>(&u);
    return __half22float2(h);
}

__device__ __forceinline__ long long get_idx(const void* ei, long long i, int is64) {
    if (is64) return ((const long long*)ei)[i];
    return (long long)((const int*)ei)[i];
}

__global__ void detect_kernel(const int* ei32) {
    int bad = 0;
    for (int i = 2 * threadIdx.x + 1; i < 4096; i += 512) bad |= ei32[i];
    int any = __syncthreads_or(bad);
    if (threadIdx.x == 0) g_is64 = (any == 0) ? 1 : 0;
}

__global__ void zero_int_kernel(int* p, int n) {
    int i = blockIdx.x * blockDim.x + threadIdx.x;
    if (i < n) p[i] = 0;
}

__global__ void hist_kernel(const void* __restrict__ ei, int E, int* __restrict__ cnt) {
    int e = blockIdx.x * blockDim.x + threadIdx.x;
    if (e >= E) return;
    int is64 = g_is64;
    long long d = get_idx(ei, (long long)E + e, is64);
    atomicAdd(&cnt[d], 1);
}

__global__ void blocksum_kernel(const int* __restrict__ cnt, int* __restrict__ bsum, int M) {
    __shared__ int s[8];
    int i = blockIdx.x * 256 + threadIdx.x;
    int v = (i < M) ? cnt[i] : 0;
#pragma unroll
    for (int o = 16; o > 0; o >>= 1) v += __shfl_xor_sync(0xffffffffu, v, o);
    if ((threadIdx.x & 31) == 0) s[threadIdx.x >> 5] = v;
    __syncthreads();
    if (threadIdx.x == 0) {
        int t = 0;
#pragma unroll
        for (int w = 0; w < 8; w++) t += s[w];
        bsum[blockIdx.x] = t;
    }
}

__global__ void scanb_kernel(int* bsum, int nb) {
    __shared__ int s[512];
    int t = threadIdx.x;
    int v = (t < nb) ? bsum[t] : 0;
    s[t] = v;
    __syncthreads();
    for (int off = 1; off < 512; off <<= 1) {
        int u = (t >= off) ? s[t - off] : 0;
        __syncthreads();
        s[t] += u;
        __syncthreads();
    }
    if (t < nb) bsum[t] = s[t] - v;
}

__global__ void scan_final_kernel(const int* __restrict__ cnt, const int* __restrict__ bsum,
                                  int* __restrict__ rowptr, int* __restrict__ cursor,
                                  float* __restrict__ inv, int M) {
    __shared__ int s[256];
    int t = threadIdx.x;
    int i = blockIdx.x * 256 + t;
    int c = (i < M) ? cnt[i] : 0;
    s[t] = c;
    __syncthreads();
    for (int off = 1; off < 256; off <<= 1) {
        int u = (t >= off) ? s[t - off] : 0;
        __syncthreads();
        s[t] += u;
        __syncthreads();
    }
    if (i < M) {
        int rp = bsum[blockIdx.x] + s[t] - c;
        rowptr[i] = rp;
        cursor[i] = rp;
        inv[i] = 1.0f / fmaxf((float)c, 1.0f);
        if (i == M - 1) rowptr[M] = rp + c;
    }
}

__global__ void fill_kernel(const void* __restrict__ ei, int E,
                            int* __restrict__ cursor, int* __restrict__ csr) {
    int e = blockIdx.x * blockDim.x + threadIdx.x;
    if (e >= E) return;
    int is64 = g_is64;
    long long s = get_idx(ei, e, is64);
    long long d = get_idx(ei, (long long)E + e, is64);
    int slot = atomicAdd(&cursor[d], 1);
    csr[slot] = (int)s;
}

__global__ void packw_kernel(const float* __restrict__ s1, int k1,
                             const float* __restrict__ s2, int k2,
                             uint32_t* __restrict__ H, int N) {
    int ktot = k1 + k2;
    int nu = ktot >> 1;
    int i = blockIdx.x * blockDim.x + threadIdx.x;
    if (i >= N * nu) return;
    int row = i / nu, j = i - row * nu;
    int f0 = 2 * j;
    float a, b;
    if (f0 < k1) { a = s1[(size_t)row * k1 + f0]; b = s1[(size_t)row * k1 + f0 + 1]; }
    else         { a = s2[(size_t)row * k2 + f0 - k1]; b = s2[(size_t)row * k2 + f0 - k1 + 1]; }
    H[i] = packh(a, b);
}

// layer3 weights: rows 0..46 Wl3, row 47 zero, rows 48..94 Wr3, row 95 zero; K=256
__global__ void packw3_kernel(const float* __restrict__ Wl3, const float* __restrict__ Wr3,
                              uint32_t* __restrict__ H) {
    int i = blockIdx.x * blockDim.x + threadIdx.x;
    if (i >= 96 * 128) return;
    int row = i >> 7, j = i & 127;
    float a = 0.f, b = 0.f;
    if (row < 47)                   { a = Wl3[row * 256 + 2 * j];        b = Wl3[row * 256 + 2 * j + 1]; }
    else if (row >= 48 && row < 95) { a = Wr3[(row - 48) * 256 + 2 * j]; b = Wr3[(row - 48) * 256 + 2 * j + 1]; }
    H[i] = packh(a, b);
}

// gather from packed fp16 source; fp32 accumulate; packed fp16 output; unroll 4
template <int NACC>
__global__ void gather_h16(const uint2* __restrict__ src, int src_ld2,
                           uint32_t* __restrict__ dH, int dst_ld,
                           const int* __restrict__ rowptr, const int* __restrict__ csr,
                           const float* __restrict__ inv, int M) {
    int node = blockIdx.x * (blockDim.x >> 5) + (threadIdx.x >> 5);
    if (node >= M) return;
    int lane = threadIdx.x & 31;
    int beg = rowptr[node], end = rowptr[node + 1];
    float s = inv[node];
    float4 acc[NACC];
#pragma unroll
    for (int i = 0; i < NACC; i++) acc[i] = make_float4(0.f, 0.f, 0.f, 0.f);
    int e = beg;
    for (; e + 3 < end; e += 4) {
        const uint2* r0 = src + (size_t)csr[e] * src_ld2;
        const uint2* r1 = src + (size_t)csr[e + 1] * src_ld2;
        const uint2* r2 = src + (size_t)csr[e + 2] * src_ld2;
        const uint2* r3 = src + (size_t)csr[e + 3] * src_ld2;
#pragma unroll
        for (int i = 0; i < NACC; i++) {
            uint2 p0 = r0[lane + 32 * i];
            uint2 p1 = r1[lane + 32 * i];
            uint2 p2 = r2[lane + 32 * i];
            uint2 p3 = r3[lane + 32 * i];
            float2 a0 = h2f(p0.x), b0 = h2f(p0.y);
            float2 a1 = h2f(p1.x), b1 = h2f(p1.y);
            float2 a2 = h2f(p2.x), b2 = h2f(p2.y);
            float2 a3 = h2f(p3.x), b3 = h2f(p3.y);
            acc[i].x += (a0.x + a1.x) + (a2.x + a3.x);
            acc[i].y += (a0.y + a1.y) + (a2.y + a3.y);
            acc[i].z += (b0.x + b1.x) + (b2.x + b3.x);
            acc[i].w += (b0.y + b1.y) + (b2.y + b3.y);
        }
    }
    for (; e < end; e++) {
        const uint2* r0 = src + (size_t)csr[e] * src_ld2;
#pragma unroll
        for (int i = 0; i < NACC; i++) {
            uint2 p0 = r0[lane + 32 * i];
            float2 a0 = h2f(p0.x), b0 = h2f(p0.y);
            acc[i].x += a0.x; acc[i].y += a0.y;
            acc[i].z += b0.x; acc[i].w += b0.y;
        }
    }
#pragma unroll
    for (int i = 0; i < NACC; i++) {
        float4 v = acc[i];
        v.x *= s; v.y *= s; v.z *= s; v.w *= s;
        int col2 = (lane + 32 * i) * 2;
        *(uint2*)(dH + (size_t)node * dst_ld + col2) =
            make_uint2(packh(v.x, v.y), packh(v.z, v.w));
    }
}

#define BROW 12

__device__ __forceinline__ uint32_t smem_u32(const void* p) {
    uint32_t a;
    asm("{ .reg .u64 t; cvta.to.shared.u64 t, %1; cvt.u32.u64 %0, t; }" : "=r"(a) : "l"(p));
    return a;
}
__device__ __forceinline__ void cpa16(uint32_t dst, const void* src, int sz) {
    asm volatile("cp.async.cg.shared.global [%0], [%1], 16, %2;"
                 :: "r"(dst), "l"(src), "r"(sz) : "memory");
}
__device__ __forceinline__ void mma_f16(float* c, uint32_t a0, uint32_t a1, uint32_t a2, uint32_t a3,
                                        uint32_t b0, uint32_t b1) {
    asm volatile(
        "mma.sync.aligned.m16n8k16.row.col.f32.f16.f16.f32 "
        "{%0,%1,%2,%3}, {%4,%5,%6,%7}, {%8,%9}, {%0,%1,%2,%3};"
        : "+f"(c[0]), "+f"(c[1]), "+f"(c[2]), "+f"(c[3])
        : "r"(a0), "r"(a1), "r"(a2), "r"(a3), "r"(b0), "r"(b1));
}

// single-term fp16 GEMM: D = A*B, A = [A1 | A2] packed fp16, B packed fp16
__global__ void __launch_bounds__(256, 2)
gemm_f16(const uint32_t* __restrict__ A1H, int K1,
         const uint32_t* __restrict__ A2H, int K2,
         const uint32_t* __restrict__ BH,
         uint32_t* __restrict__ CH, int ldch,
         int M, int N, int do_relu) {
    __shared__ uint32_t sbuf[2][2][128 * BROW];

    const int tid = threadIdx.x;
    const int wid = tid >> 5;
    const int lid = tid & 31;
    const int gID = lid >> 2;
    const int tig = lid & 3;
    const int warp_m = wid & 3;
    const int warp_n = wid >> 2;
    const int m_base = blockIdx.y * 128;
    const int n_base = blockIdx.x * 128;
    const int K = K1 + K2;
    const int nchunks = K >> 4;
    const int ldb = K >> 1;
    const int k1u = K1 >> 1;
    const uint32_t sb = smem_u32(&sbuf[0][0][0]);

    const int crow = tid >> 1;
    const int chalf = tid & 1;
    const int mg = m_base + crow;
    const int ng = n_base + crow;
    const int szA = (mg < M) ? 16 : 0;
    const int szB = (ng < N) ? 16 : 0;
    const uint32_t doff = (uint32_t)(crow * BROW + chalf * 4) * 4;

    float acc[2][8][4];
#pragma unroll
    for (int mi = 0; mi < 2; mi++)
#pragma unroll
        for (int ni = 0; ni < 8; ni++)
#pragma unroll
            for (int j = 0; j < 4; j++) acc[mi][ni][j] = 0.f;

    auto copy_chunk = [&](int kc, int s) {
        int ku = (kc << 3) + chalf * 4;
        const uint32_t* ah;
        if (ku < k1u) ah = A1H + (size_t)mg * k1u + ku;
        else          ah = A2H + (size_t)mg * (K2 >> 1) + (ku - k1u);
        uint32_t base = sb + (uint32_t)(s * 2) * (128 * BROW * 4);
        cpa16(base + doff,                    ah, szA);
        const uint32_t* bh = BH + (size_t)ng * ldb + ku;
        cpa16(base + 128 * BROW * 4 + doff,   bh, szB);
    };

    copy_chunk(0, 0);
    asm volatile("cp.async.commit_group;" ::: "memory");

    for (int kc = 0; kc < nchunks; kc++) {
        int s = kc & 1;
        if (kc + 1 < nchunks) {
            copy_chunk(kc + 1, (kc + 1) & 1);
            asm volatile("cp.async.commit_group;" ::: "memory");
            asm volatile("cp.async.wait_group 1;" ::: "memory");
        } else {
            asm volatile("cp.async.wait_group 0;" ::: "memory");
        }
        __syncthreads();

        const uint32_t* Ah = sbuf[s][0];
        const uint32_t* Bh = sbuf[s][1];

        uint32_t ah[2][4];
#pragma unroll
        for (int mi = 0; mi < 2; mi++) {
            int rm = warp_m * 32 + mi * 16;
            int r0 = (rm + gID) * BROW + tig;
            int r1 = (rm + gID + 8) * BROW + tig;
            ah[mi][0] = Ah[r0];     ah[mi][1] = Ah[r1];
            ah[mi][2] = Ah[r0 + 4]; ah[mi][3] = Ah[r1 + 4];
        }
#pragma unroll
        for (int ni = 0; ni < 8; ni++) {
            int nn = warp_n * 64 + ni * 8 + gID;
            int o = nn * BROW + tig;
            uint32_t bh0 = Bh[o], bh1 = Bh[o + 4];
#pragma unroll
            for (int mi = 0; mi < 2; mi++) {
                mma_f16(acc[mi][ni], ah[mi][0], ah[mi][1], ah[mi][2], ah[mi][3], bh0, bh1);
            }
        }
        __syncthreads();
    }

#pragma unroll
    for (int mi = 0; mi < 2; mi++) {
#pragma unroll
        for (int ni = 0; ni < 8; ni++) {
            int col = n_base + warp_n * 64 + ni * 8 + 2 * tig;
            if (col >= N) continue;
            int r0 = m_base + warp_m * 32 + mi * 16 + gID;
            int r1 = r0 + 8;
            float2 v0 = make_float2(acc[mi][ni][0], acc[mi][ni][1]);
            float2 v1 = make_float2(acc[mi][ni][2], acc[mi][ni][3]);
            if (do_relu) {
                v0.x = fmaxf(v0.x, 0.f); v0.y = fmaxf(v0.y, 0.f);
                v1.x = fmaxf(v1.x, 0.f); v1.y = fmaxf(v1.y, 0.f);
            }
            if (r0 < M) CH[(size_t)r0 * ldch + (col >> 1)] = packh(v0.x, v0.y);
            if (r1 < M) CH[(size_t)r1 * ldch + (col >> 1)] = packh(v1.x, v1.y);
        }
    }
}

// fused layer-3 gather + log_softmax. zrH row: u32 0..23 = z cols 0..47 (47 pad),
// u32 24..47 = r cols 0..47 (47 pad). One warp per node; lanes 0..23 active for data.
__global__ void final_fused(const uint32_t* __restrict__ zrH,
                            const int* __restrict__ rowptr, const int* __restrict__ csr,
                            const float* __restrict__ inv, float* __restrict__ out, int M) {
    int node = blockIdx.x * (blockDim.x >> 5) + (threadIdx.x >> 5);
    if (node >= M) return;
    int lane = threadIdx.x & 31;
    int beg = rowptr[node], end = rowptr[node + 1];
    bool zact = lane < 24;
    float zx = 0.f, zy = 0.f;
    int e = beg;
    for (; e + 3 < end; e += 4) {
        if (zact) {
            float2 a0 = h2f(zrH[(size_t)csr[e]     * 48 + lane]);
            float2 a1 = h2f(zrH[(size_t)csr[e + 1] * 48 + lane]);
            float2 a2 = h2f(zrH[(size_t)csr[e + 2] * 48 + lane]);
            float2 a3 = h2f(zrH[(size_t)csr[e + 3] * 48 + lane]);
            zx += (a0.x + a1.x) + (a2.x + a3.x);
            zy += (a0.y + a1.y) + (a2.y + a3.y);
        }
    }
    for (; e < end; e++) {
        if (zact) {
            float2 a0 = h2f(zrH[(size_t)csr[e] * 48 + lane]);
            zx += a0.x; zy += a0.y;
        }
    }
    float s = inv[node];
    float v1 = -CUDART_INF_F, v2 = -CUDART_INF_F;
    if (zact) {
        float2 rf = h2f(zrH[(size_t)node * 48 + 24 + lane]);
        v1 = zx * s + rf.x;                       // col 2*lane  (<47 always for lane<24)
        if (2 * lane + 1 < 47) v2 = zy * s + rf.y; // col 2*lane+1
    }
    float mx = fmaxf(v1, v2);
#pragma unroll
    for (int o = 16; o > 0; o >>= 1) mx = fmaxf(mx, __shfl_xor_sync(0xffffffffu, mx, o));
    float se = 0.f;
    if (v1 > -CUDART_INF_F) se += expf(v1 - mx);
    if (v2 > -CUDART_INF_F) se += expf(v2 - mx);
#pragma unroll
    for (int o = 16; o > 0; o >>= 1) se += __shfl_xor_sync(0xffffffffu, se, o);
    float lse = logf(se);
    if (zact) {
        out[(size_t)node * 47 + 2 * lane] = v1 - mx - lse;
        if (2 * lane + 1 < 47) out[(size_t)node * 47 + 2 * lane + 1] = v2 - mx - lse;
    }
}

extern "C" void kernel_launch(void* const* d_in, const int* in_sizes, int n_in,
                              void* d_out, int out_size) {
    const float* x   = (const float*)d_in[0];
    const float* Wl1 = (const float*)d_in[1];
    const float* Wr1 = (const float*)d_in[2];
    const float* Wl2 = (const float*)d_in[3];
    const float* Wr2 = (const float*)d_in[4];
    const float* Wl3 = (const float*)d_in[5];
    const float* Wr3 = (const float*)d_in[6];
    const void*  ei  = d_in[7];
    const int E = in_sizes[7] / 2;
    const int M = in_sizes[0] / C_IN;
    float* out = (float*)d_out;

    float *inv;
    uint32_t *aggH, *xH, *h1H, *h2H, *zrH;
    uint32_t *W1H, *W2H, *W3H;
    int *cnt, *rowptr, *cursor, *csr, *bsum;
    cudaGetSymbolAddress((void**)&inv,    g_inv);
    cudaGetSymbolAddress((void**)&aggH,   g_aggH);
    cudaGetSymbolAddress((void**)&xH,     g_xH);
    cudaGetSymbolAddress((void**)&h1H,    g_h1H);
    cudaGetSymbolAddress((void**)&h2H,    g_h2H);
    cudaGetSymbolAddress((void**)&zrH,    g_zrH);
    cudaGetSymbolAddress((void**)&W1H,    g_W1H);
    cudaGetSymbolAddress((void**)&W2H,    g_W2H);
    cudaGetSymbolAddress((void**)&W3H,    g_W3H);
    cudaGetSymbolAddress((void**)&cnt,    g_cnt);
    cudaGetSymbolAddress((void**)&rowptr, g_rowptr);
    cudaGetSymbolAddress((void**)&cursor, g_cursor);
    cudaGetSymbolAddress((void**)&csr,    g_csr);
    cudaGetSymbolAddress((void**)&bsum,   g_bsum);

    detect_kernel<<<1, 256>>>((const int*)ei);

    const int nb = (M + 255) / 256;
    zero_int_kernel<<<nb, 256>>>(cnt, M);
    hist_kernel<<<(E + 255) / 256, 256>>>(ei, E, cnt);
    blocksum_kernel<<<nb, 256>>>(cnt, bsum, M);
    scanb_kernel<<<1, 512>>>(bsum, nb);
    scan_final_kernel<<<nb, 256>>>(cnt, bsum, rowptr, cursor, inv, M);
    fill_kernel<<<(E + 255) / 256, 256>>>(ei, E, cursor, csr);

    packw_kernel<<<(256 * 128 + 255) / 256, 256>>>(Wl1, 128, Wr1, 128, W1H, 256);
    packw_kernel<<<(256 * 256 + 255) / 256, 256>>>(Wl2, 256, Wr2, 256, W2H, 256);
    packw3_kernel<<<(96 * 128 + 255) / 256, 256>>>(Wl3, Wr3, W3H);
    packw_kernel<<<((M * 64) + 255) / 256, 256>>>(x, 128, (const float*)nullptr, 0, xH, M);

    const int gat_blocks = (M + 7) / 8;
    const int grid_m = (M + 127) / 128;

    // layer 1
    gather_h16<1><<<gat_blocks, 256>>>((const uint2*)xH, 32,
                                       aggH, 64, rowptr, csr, inv, M);
    gemm_f16<<<dim3(2, grid_m), 256>>>(aggH, 128, xH, 128,
                                       W1H, h1H, 128, M, 256, 1);

    // layer 2
    gather_h16<2><<<gat_blocks, 256>>>((const uint2*)h1H, 64,
                                       aggH, 128, rowptr, csr, inv, M);
    gemm_f16<<<dim3(2, grid_m), 256>>>(aggH, 256, h1H, 256,
                                       W2H, h2H, 128, M, 256, 1);

    // layer 3: transform-first, packed fp16 zr; fused gather + log_softmax
    gemm_f16<<<dim3(1, grid_m), 256>>>(h2H, 256, (const uint32_t*)nullptr, 0,
                                       W3H, zrH, 48, M, 96, 0);
    final_fused<<<gat_blocks, 256>>>(zrH, rowptr, csr, inv, out, M);
}

// round 14
// speedup vs baseline: 1.7363x; 1.0001x over previous
#include <cuda_runtime.h>
#include <cuda_fp16.h>
#include <cstdint>
#include <math_constants.h>

#define NNODES 50000
#define NEDGES 600000
#define C_IN   128
#define C_HID  256
#define C_OUT  47

__device__ __align__(128) float    g_inv [NNODES];
__device__ __align__(128) uint32_t g_aggH[(size_t)NNODES * 128];
__device__ __align__(128) uint32_t g_xH  [(size_t)NNODES * 64];
__device__ __align__(128) uint32_t g_h1H [(size_t)NNODES * 128];
__device__ __align__(128) uint32_t g_h2H [(size_t)NNODES * 128];
__device__ __align__(128) uint32_t g_zrH [(size_t)NNODES * 48];
__device__ __align__(128) uint32_t g_W1H [256 * 128];
__device__ __align__(128) uint32_t g_W2H [256 * 256];
__device__ __align__(128) uint32_t g_W3H [96 * 128];
__device__ __align__(128) int      g_cnt [NNODES];
__device__ __align__(128) int      g_rowptr[NNODES + 1];
__device__ __align__(128) int      g_cursor[NNODES];
__device__ __align__(128) int      g_csr [NEDGES];
__device__ __align__(128) int      g_state[256];
__device__ __align__(128) int      g_aggv [256];
__device__ __align__(128) int      g_prefv[256];
__device__ int g_is64;

__device__ __forceinline__ uint32_t packh(float a, float b) {
    __half2 h = __floats2half2_rn(a, b);
    return *reinterpret_cast<uint32_t*>(&h);
}
__device__ __forceinline__ float2 h2f(uint32_t u) {
    __half2 h = *reinterpret_cast<__half2*>(&u);
    return __half22float2(h);
}

__device__ __forceinline__ long long get_idx(const void* ei, long long i, int is64) {
    if (is64) return ((const long long*)ei)[i];
    return (long long)((const int*)ei)[i];
}

// ---- fused prep: detect(int64?) + zero cnt/state + pack W1/W2/W3/x ----
#define A_W1 32768
#define A_W2 65536
#define A_W3 12288

__global__ void prep_kernel(const int* __restrict__ ei32,
                            const float* __restrict__ x,
                            const float* __restrict__ Wl1, const float* __restrict__ Wr1,
                            const float* __restrict__ Wl2, const float* __restrict__ Wr2,
                            const float* __restrict__ Wl3, const float* __restrict__ Wr3,
                            uint32_t* __restrict__ xH, uint32_t* __restrict__ W1H,
                            uint32_t* __restrict__ W2H, uint32_t* __restrict__ W3H,
                            int* __restrict__ cnt, int* __restrict__ state, int M) {
    if (blockIdx.x == 0) {
        int bad = 0;
        for (int i = 2 * threadIdx.x + 1; i < 4096; i += 512) bad |= ei32[i];
        int any = __syncthreads_or(bad);
        if (threadIdx.x == 0) g_is64 = (any == 0) ? 1 : 0;
    }
    long long gidx = blockIdx.x * 256LL + threadIdx.x;
    const long long T0 = M;                 // cnt zero
    const long long T1 = T0 + 256;          // state zero
    const long long T2 = T1 + A_W1;         // W1 pack
    const long long T3 = T2 + A_W2;         // W2 pack
    const long long T4 = T3 + A_W3;         // W3 pack
    const long long T5 = T4 + (long long)M * 64;  // x pack
    if (gidx >= T5) return;
    if (gidx < T0) {
        cnt[gidx] = 0;
    } else if (gidx < T1) {
        state[gidx - T0] = 0;
    } else if (gidx < T2) {
        int i = (int)(gidx - T1);
        int row = i >> 7, j = i & 127;
        int f0 = 2 * j;
        float a, b;
        if (f0 < 128) { a = Wl1[row * 128 + f0]; b = Wl1[row * 128 + f0 + 1]; }
        else          { a = Wr1[row * 128 + f0 - 128]; b = Wr1[row * 128 + f0 - 127]; }
        W1H[i] = packh(a, b);
    } else if (gidx < T3) {
        int i = (int)(gidx - T2);
        int row = i >> 8, j = i & 255;
        int f0 = 2 * j;
        float a, b;
        if (f0 < 256) { a = Wl2[row * 256 + f0]; b = Wl2[row * 256 + f0 + 1]; }
        else          { a = Wr2[row * 256 + f0 - 256]; b = Wr2[row * 256 + f0 - 255]; }
        W2H[i] = packh(a, b);
    } else if (gidx < T4) {
        int i = (int)(gidx - T3);
        int row = i >> 7, j = i & 127;
        float a = 0.f, b = 0.f;
        if (row < 47)                   { a = Wl3[row * 256 + 2 * j];        b = Wl3[row * 256 + 2 * j + 1]; }
        else if (row >= 48 && row < 95) { a = Wr3[(row - 48) * 256 + 2 * j]; b = Wr3[(row - 48) * 256 + 2 * j + 1]; }
        W3H[i] = packh(a, b);
    } else {
        long long i = gidx - T4;
        int row = (int)(i >> 6), j = (int)(i & 63);
        float a = x[(size_t)row * 128 + 2 * j];
        float b = x[(size_t)row * 128 + 2 * j + 1];
        xH[i] = packh(a, b);
    }
}

__global__ void hist_kernel(const void* __restrict__ ei, int E, int* __restrict__ cnt) {
    int e = blockIdx.x * blockDim.x + threadIdx.x;
    if (e >= E) return;
    int is64 = g_is64;
    long long d = get_idx(ei, (long long)E + e, is64);
    atomicAdd(&cnt[d], 1);
}

// single-pass decoupled-lookback scan: rowptr/cursor/inv in one launch
__global__ void scan_onepass(const int* __restrict__ cnt,
                             int* __restrict__ rowptr, int* __restrict__ cursor,
                             float* __restrict__ inv,
                             volatile int* state, volatile int* aggval, volatile int* prefval,
                             int M) {
    __shared__ int s[256];
    __shared__ int sbase;
    int b = blockIdx.x;
    int t = threadIdx.x;
    int i = b * 256 + t;
    int c = (i < M) ? cnt[i] : 0;
    s[t] = c;
    __syncthreads();
    for (int off = 1; off < 256; off <<= 1) {
        int u = (t >= off) ? s[t - off] : 0;
        __syncthreads();
        s[t] += u;
        __syncthreads();
    }
    int total = s[255];
    if (t == 0) {
        if (b == 0) {
            prefval[0] = total;
            __threadfence();
            state[0] = 2;
            sbase = 0;
        } else {
            aggval[b] = total;
            __threadfence();
            state[b] = 1;
            int base = 0;
            int j = b - 1;
            while (true) {
                int st;
                do { st = state[j]; } while (st == 0);
                if (st == 2) { base += prefval[j]; break; }
                base += aggval[j];
                j--;
            }
            prefval[b] = base + total;
            __threadfence();
            state[b] = 2;
            sbase = base;
        }
    }
    __syncthreads();
    int base = sbase;
    if (i < M) {
        int rp = base + s[t] - c;
        rowptr[i] = rp;
        cursor[i] = rp;
        inv[i] = 1.0f / fmaxf((float)c, 1.0f);
        if (i == M - 1) rowptr[M] = rp + c;
    }
}

__global__ void fill_kernel(const void* __restrict__ ei, int E,
                            int* __restrict__ cursor, int* __restrict__ csr) {
    int e = blockIdx.x * blockDim.x + threadIdx.x;
    if (e >= E) return;
    int is64 = g_is64;
    long long s = get_idx(ei, e, is64);
    long long d = get_idx(ei, (long long)E + e, is64);
    int slot = atomicAdd(&cursor[d], 1);
    csr[slot] = (int)s;
}

// gather from packed fp16 source; fp32 accumulate; packed fp16 output; unroll 4
template <int NACC>
__global__ void gather_h16(const uint2* __restrict__ src, int src_ld2,
                           uint32_t* __restrict__ dH, int dst_ld,
                           const int* __restrict__ rowptr, const int* __restrict__ csr,
                           const float* __restrict__ inv, int M) {
    int node = blockIdx.x * (blockDim.x >> 5) + (threadIdx.x >> 5);
    if (node >= M) return;
    int lane = threadIdx.x & 31;
    int beg = rowptr[node], end = rowptr[node + 1];
    float s = inv[node];
    float4 acc[NACC];
#pragma unroll
    for (int i = 0; i < NACC; i++) acc[i] = make_float4(0.f, 0.f, 0.f, 0.f);
    int e = beg;
    for (; e + 3 < end; e += 4) {
        const uint2* r0 = src + (size_t)csr[e] * src_ld2;
        const uint2* r1 = src + (size_t)csr[e + 1] * src_ld2;
        const uint2* r2 = src + (size_t)csr[e + 2] * src_ld2;
        const uint2* r3 = src + (size_t)csr[e + 3] * src_ld2;
#pragma unroll
        for (int i = 0; i < NACC; i++) {
            uint2 p0 = r0[lane + 32 * i];
            uint2 p1 = r1[lane + 32 * i];
            uint2 p2 = r2[lane + 32 * i];
            uint2 p3 = r3[lane + 32 * i];
            float2 a0 = h2f(p0.x), b0 = h2f(p0.y);
            float2 a1 = h2f(p1.x), b1 = h2f(p1.y);
            float2 a2 = h2f(p2.x), b2 = h2f(p2.y);
            float2 a3 = h2f(p3.x), b3 = h2f(p3.y);
            acc[i].x += (a0.x + a1.x) + (a2.x + a3.x);
            acc[i].y += (a0.y + a1.y) + (a2.y + a3.y);
            acc[i].z += (b0.x + b1.x) + (b2.x + b3.x);
            acc[i].w += (b0.y + b1.y) + (b2.y + b3.y);
        }
    }
    for (; e < end; e++) {
        const uint2* r0 = src + (size_t)csr[e] * src_ld2;
#pragma unroll
        for (int i = 0; i < NACC; i++) {
            uint2 p0 = r0[lane + 32 * i];
            float2 a0 = h2f(p0.x), b0 = h2f(p0.y);
            acc[i].x += a0.x; acc[i].y += a0.y;
            acc[i].z += b0.x; acc[i].w += b0.y;
        }
    }
#pragma unroll
    for (int i = 0; i < NACC; i++) {
        float4 v = acc[i];
        v.x *= s; v.y *= s; v.z *= s; v.w *= s;
        int col2 = (lane + 32 * i) * 2;
        *(uint2*)(dH + (size_t)node * dst_ld + col2) =
            make_uint2(packh(v.x, v.y), packh(v.z, v.w));
    }
}

#define BROW 12

__device__ __forceinline__ uint32_t smem_u32(const void* p) {
    uint32_t a;
    asm("{ .reg .u64 t; cvta.to.shared.u64 t, %1; cvt.u32.u64 %0, t; }" : "=r"(a) : "l"(p));
    return a;
}
__device__ __forceinline__ void cpa16(uint32_t dst, const void* src, int sz) {
    asm volatile("cp.async.cg.shared.global [%0], [%1], 16, %2;"
                 :: "r"(dst), "l"(src), "r"(sz) : "memory");
}
__device__ __forceinline__ void mma_f16(float* c, uint32_t a0, uint32_t a1, uint32_t a2, uint32_t a3,
                                        uint32_t b0, uint32_t b1) {
    asm volatile(
        "mma.sync.aligned.m16n8k16.row.col.f32.f16.f16.f32 "
        "{%0,%1,%2,%3}, {%4,%5,%6,%7}, {%8,%9}, {%0,%1,%2,%3};"
        : "+f"(c[0]), "+f"(c[1]), "+f"(c[2]), "+f"(c[3])
        : "r"(a0), "r"(a1), "r"(a2), "r"(a3), "r"(b0), "r"(b1));
}

// single-term fp16 GEMM: D = A*B, A = [A1 | A2] packed fp16, B packed fp16
__global__ void __launch_bounds__(256, 2)
gemm_f16(const uint32_t* __restrict__ A1H, int K1,
         const uint32_t* __restrict__ A2H, int K2,
         const uint32_t* __restrict__ BH,
         uint32_t* __restrict__ CH, int ldch,
         int M, int N, int do_relu) {
    __shared__ uint32_t sbuf[2][2][128 * BROW];

    const int tid = threadIdx.x;
    const int wid = tid >> 5;
    const int lid = tid & 31;
    const int gID = lid >> 2;
    const int tig = lid & 3;
    const int warp_m = wid & 3;
    const int warp_n = wid >> 2;
    const int m_base = blockIdx.y * 128;
    const int n_base = blockIdx.x * 128;
    const int K = K1 + K2;
    const int nchunks = K >> 4;
    const int ldb = K >> 1;
    const int k1u = K1 >> 1;
    const uint32_t sb = smem_u32(&sbuf[0][0][0]);

    const int crow = tid >> 1;
    const int chalf = tid & 1;
    const int mg = m_base + crow;
    const int ng = n_base + crow;
    const int szA = (mg < M) ? 16 : 0;
    const int szB = (ng < N) ? 16 : 0;
    const uint32_t doff = (uint32_t)(crow * BROW + chalf * 4) * 4;

    float acc[2][8][4];
#pragma unroll
    for (int mi = 0; mi < 2; mi++)
#pragma unroll
        for (int ni = 0; ni < 8; ni++)
#pragma unroll
            for (int j = 0; j < 4; j++) acc[mi][ni][j] = 0.f;

    auto copy_chunk = [&](int kc, int s) {
        int ku = (kc << 3) + chalf * 4;
        const uint32_t* ah;
        if (ku < k1u) ah = A1H + (size_t)mg * k1u + ku;
        else          ah = A2H + (size_t)mg * (K2 >> 1) + (ku - k1u);
        uint32_t base = sb + (uint32_t)(s * 2) * (128 * BROW * 4);
        cpa16(base + doff,                    ah, szA);
        const uint32_t* bh = BH + (size_t)ng * ldb + ku;
        cpa16(base + 128 * BROW * 4 + doff,   bh, szB);
    };

    copy_chunk(0, 0);
    asm volatile("cp.async.commit_group;" ::: "memory");

    for (int kc = 0; kc < nchunks; kc++) {
        int s = kc & 1;
        if (kc + 1 < nchunks) {
            copy_chunk(kc + 1, (kc + 1) & 1);
            asm volatile("cp.async.commit_group;" ::: "memory");
            asm volatile("cp.async.wait_group 1;" ::: "memory");
        } else {
            asm volatile("cp.async.wait_group 0;" ::: "memory");
        }
        __syncthreads();

        const uint32_t* Ah = sbuf[s][0];
        const uint32_t* Bh = sbuf[s][1];

        uint32_t ah[2][4];
#pragma unroll
        for (int mi = 0; mi < 2; mi++) {
            int rm = warp_m * 32 + mi * 16;
            int r0 = (rm + gID) * BROW + tig;
            int r1 = (rm + gID + 8) * BROW + tig;
            ah[mi][0] = Ah[r0];     ah[mi][1] = Ah[r1];
            ah[mi][2] = Ah[r0 + 4]; ah[mi][3] = Ah[r1 + 4];
        }
#pragma unroll
        for (int ni = 0; ni < 8; ni++) {
            int nn = warp_n * 64 + ni * 8 + gID;
            int o = nn * BROW + tig;
            uint32_t bh0 = Bh[o], bh1 = Bh[o + 4];
#pragma unroll
            for (int mi = 0; mi < 2; mi++) {
                mma_f16(acc[mi][ni], ah[mi][0], ah[mi][1], ah[mi][2], ah[mi][3], bh0, bh1);
            }
        }
        __syncthreads();
    }

#pragma unroll
    for (int mi = 0; mi < 2; mi++) {
#pragma unroll
        for (int ni = 0; ni < 8; ni++) {
            int col = n_base + warp_n * 64 + ni * 8 + 2 * tig;
            if (col >= N) continue;
            int r0 = m_base + warp_m * 32 + mi * 16 + gID;
            int r1 = r0 + 8;
            float2 v0 = make_float2(acc[mi][ni][0], acc[mi][ni][1]);
            float2 v1 = make_float2(acc[mi][ni][2], acc[mi][ni][3]);
            if (do_relu) {
                v0.x = fmaxf(v0.x, 0.f); v0.y = fmaxf(v0.y, 0.f);
                v1.x = fmaxf(v1.x, 0.f); v1.y = fmaxf(v1.y, 0.f);
            }
            if (r0 < M) CH[(size_t)r0 * ldch + (col >> 1)] = packh(v0.x, v0.y);
            if (r1 < M) CH[(size_t)r1 * ldch + (col >> 1)] = packh(v1.x, v1.y);
        }
    }
}

// fused layer-3 gather + log_softmax
__global__ void final_fused(const uint32_t* __restrict__ zrH,
                            const int* __restrict__ rowptr, const int* __restrict__ csr,
                            const float* __restrict__ inv, float* __restrict__ out, int M) {
    int node = blockIdx.x * (blockDim.x >> 5) + (threadIdx.x >> 5);
    if (node >= M) return;
    int lane = threadIdx.x & 31;
    int beg = rowptr[node], end = rowptr[node + 1];
    bool zact = lane < 24;
    float zx = 0.f, zy = 0.f;
    int e = beg;
    for (; e + 3 < end; e += 4) {
        if (zact) {
            float2 a0 = h2f(zrH[(size_t)csr[e]     * 48 + lane]);
            float2 a1 = h2f(zrH[(size_t)csr[e + 1] * 48 + lane]);
            float2 a2 = h2f(zrH[(size_t)csr[e + 2] * 48 + lane]);
            float2 a3 = h2f(zrH[(size_t)csr[e + 3] * 48 + lane]);
            zx += (a0.x + a1.x) + (a2.x + a3.x);
            zy += (a0.y + a1.y) + (a2.y + a3.y);
        }
    }
    for (; e < end; e++) {
        if (zact) {
            float2 a0 = h2f(zrH[(size_t)csr[e] * 48 + lane]);
            zx += a0.x; zy += a0.y;
        }
    }
    float s = inv[node];
    float v1 = -CUDART_INF_F, v2 = -CUDART_INF_F;
    if (zact) {
        float2 rf = h2f(zrH[(size_t)node * 48 + 24 + lane]);
        v1 = zx * s + rf.x;
        if (2 * lane + 1 < 47) v2 = zy * s + rf.y;
    }
    float mx = fmaxf(v1, v2);
#pragma unroll
    for (int o = 16; o > 0; o >>= 1) mx = fmaxf(mx, __shfl_xor_sync(0xffffffffu, mx, o));
    float se = 0.f;
    if (v1 > -CUDART_INF_F) se += expf(v1 - mx);
    if (v2 > -CUDART_INF_F) se += expf(v2 - mx);
#pragma unroll
    for (int o = 16; o > 0; o >>= 1) se += __shfl_xor_sync(0xffffffffu, se, o);
    float lse = logf(se);
    if (zact) {
        out[(size_t)node * 47 + 2 * lane] = v1 - mx - lse;
        if (2 * lane + 1 < 47) out[(size_t)node * 47 + 2 * lane + 1] = v2 - mx - lse;
    }
}

extern "C" void kernel_launch(void* const* d_in, const int* in_sizes, int n_in,
                              void* d_out, int out_size) {
    const float* x   = (const float*)d_in[0];
    const float* Wl1 = (const float*)d_in[1];
    const float* Wr1 = (const float*)d_in[2];
    const float* Wl2 = (const float*)d_in[3];
    const float* Wr2 = (const float*)d_in[4];
    const float* Wl3 = (const float*)d_in[5];
    const float* Wr3 = (const float*)d_in[6];
    const void*  ei  = d_in[7];
    const int E = in_sizes[7] / 2;
    const int M = in_sizes[0] / C_IN;
    float* out = (float*)d_out;

    float *inv;
    uint32_t *aggH, *xH, *h1H, *h2H, *zrH;
    uint32_t *W1H, *W2H, *W3H;
    int *cnt, *rowptr, *cursor, *csr, *state, *aggv, *prefv;
    cudaGetSymbolAddress((void**)&inv,    g_inv);
    cudaGetSymbolAddress((void**)&aggH,   g_aggH);
    cudaGetSymbolAddress((void**)&xH,     g_xH);
    cudaGetSymbolAddress((void**)&h1H,    g_h1H);
    cudaGetSymbolAddress((void**)&h2H,    g_h2H);
    cudaGetSymbolAddress((void**)&zrH,    g_zrH);
    cudaGetSymbolAddress((void**)&W1H,    g_W1H);
    cudaGetSymbolAddress((void**)&W2H,    g_W2H);
    cudaGetSymbolAddress((void**)&W3H,    g_W3H);
    cudaGetSymbolAddress((void**)&cnt,    g_cnt);
    cudaGetSymbolAddress((void**)&rowptr, g_rowptr);
    cudaGetSymbolAddress((void**)&cursor, g_cursor);
    cudaGetSymbolAddress((void**)&csr,    g_csr);
    cudaGetSymbolAddress((void**)&state,  g_state);
    cudaGetSymbolAddress((void**)&aggv,   g_aggv);
    cudaGetSymbolAddress((void**)&prefv,  g_prefv);

    // prep: detect + zeroes + all packs in one launch
    long long tot = (long long)M + 256 + A_W1 + A_W2 + A_W3 + (long long)M * 64;
    int prep_blocks = (int)((tot + 255) / 256);
    prep_kernel<<<prep_blocks, 256>>>((const int*)ei, x, Wl1, Wr1, Wl2, Wr2, Wl3, Wr3,
                                      xH, W1H, W2H, W3H, cnt, state, M);

    hist_kernel<<<(E + 255) / 256, 256>>>(ei, E, cnt);

    const int nb = (M + 255) / 256;
    scan_onepass<<<nb, 256>>>(cnt, rowptr, cursor, inv, state, aggv, prefv, M);

    fill_kernel<<<(E + 255) / 256, 256>>>(ei, E, cursor, csr);

    const int gat_blocks = (M + 7) / 8;
    const int grid_m = (M + 127) / 128;

    // layer 1
    gather_h16<1><<<gat_blocks, 256>>>((const uint2*)xH, 32,
                                       aggH, 64, rowptr, csr, inv, M);
    gemm_f16<<<dim3(2, grid_m), 256>>>(aggH, 128, xH, 128,
                                       W1H, h1H, 128, M, 256, 1);

    // layer 2
    gather_h16<2><<<gat_blocks, 256>>>((const uint2*)h1H, 64,
                                       aggH, 128, rowptr, csr, inv, M);
    gemm_f16<<<dim3(2, grid_m), 256>>>(aggH, 256, h1H, 256,
                                       W2H, h2H, 128, M, 256, 1);

    // layer 3: transform-first, packed fp16 zr; fused gather + log_softmax
    gemm_f16<<<dim3(1, grid_m), 256>>>(h2H, 256, (const uint32_t*)nullptr, 0,
                                       W3H, zrH, 48, M, 96, 0);
    final_fused<<<gat_blocks, 256>>>(zrH, rowptr, csr, inv, out, M);
}